// round 1
// baseline (speedup 1.0000x reference)
#include <cuda_runtime.h>

#define NN 50000
#define EDGE_TILE 64
#define THREADS 256

// ---- scratch (static device globals: allocation-free) ----
// g_P layout: slot-major, g_P[slot*NN*64 + node*64 + d]
// slots: 0 e_W1_i, 1 e_W1_j, 2 e_gW1_i, 3 e_gW1_j, 4 n_W1_i, 5 n_W1_j, 6 n_gW1_i, 7 n_gW1_j
__device__ float g_P[(size_t)8 * NN * 64];
__device__ float g_agg[(size_t)NN * 64];

__device__ __forceinline__ float sigm_(float x) { return 1.0f / (1.0f + __expf(-x)); }
__device__ __forceinline__ float silu_(float x) { return x * sigm_(x); }

// ============================================================
// Kernel A: node projections.  g_P[slot][node] = nf[node] @ Wblk
// grid: (ceil(NN/64), 8), 256 threads
// ============================================================
__global__ __launch_bounds__(256) void proj_kernel(
    const float* __restrict__ nf,
    const float* __restrict__ eW1, const float* __restrict__ egW1,
    const float* __restrict__ nW1, const float* __restrict__ ngW1)
{
    __shared__ float sNF[64 * 64];
    __shared__ float sW[64 * 64];

    int slot = blockIdx.y;
    const float* W;
    int roff;
    switch (slot) {
        case 0: W = eW1;  roff = 0;   break;
        case 1: W = eW1;  roff = 128; break;
        case 2: W = egW1; roff = 0;   break;
        case 3: W = egW1; roff = 128; break;
        case 4: W = nW1;  roff = 0;   break;
        case 5: W = nW1;  roff = 128; break;
        case 6: W = ngW1; roff = 0;   break;
        default: W = ngW1; roff = 128; break;
    }

    int tid = threadIdx.x;
    int m0 = blockIdx.x * 64;
    const float4* Wv = (const float4*)W;
    const float4* nfv = (const float4*)nf;

    for (int i = tid; i < 1024; i += 256) {
        ((float4*)sW)[i] = Wv[roff * 16 + i];
        int m = i >> 4;
        float4 v = make_float4(0.f, 0.f, 0.f, 0.f);
        if (m0 + m < NN) v = nfv[(size_t)(m0 + m) * 16 + (i & 15)];
        ((float4*)sNF)[i] = v;
    }
    __syncthreads();

    int tx = tid & 15, ty = tid >> 4;
    int n0 = 4 * tx;
    float acc[4][4] = {};

    #pragma unroll 16
    for (int k = 0; k < 64; k++) {
        float a0 = sNF[(4 * ty + 0) * 64 + k];
        float a1 = sNF[(4 * ty + 1) * 64 + k];
        float a2 = sNF[(4 * ty + 2) * 64 + k];
        float a3 = sNF[(4 * ty + 3) * 64 + k];
        float4 b = *(const float4*)&sW[k * 64 + n0];
        acc[0][0] += a0 * b.x; acc[0][1] += a0 * b.y; acc[0][2] += a0 * b.z; acc[0][3] += a0 * b.w;
        acc[1][0] += a1 * b.x; acc[1][1] += a1 * b.y; acc[1][2] += a1 * b.z; acc[1][3] += a1 * b.w;
        acc[2][0] += a2 * b.x; acc[2][1] += a2 * b.y; acc[2][2] += a2 * b.z; acc[2][3] += a2 * b.w;
        acc[3][0] += a3 * b.x; acc[3][1] += a3 * b.y; acc[3][2] += a3 * b.z; acc[3][3] += a3 * b.w;
    }

    float* outp = g_P + (size_t)slot * NN * 64;
    #pragma unroll
    for (int i = 0; i < 4; i++) {
        int m = m0 + 4 * ty + i;
        if (m < NN) {
            *(float4*)&outp[(size_t)m * 64 + n0] =
                make_float4(acc[i][0], acc[i][1], acc[i][2], acc[i][3]);
        }
    }
}

// ============================================================
// zero g_agg
// ============================================================
__global__ void zero_agg_kernel() {
    size_t i = (size_t)blockIdx.x * 256 + threadIdx.x;
    if (i < (size_t)NN * 64) g_agg[i] = 0.f;
}

// ============================================================
// Edge/message kernel.  NODE=false: edge (bond) update, writes new_edge.
// NODE=true: node message pass, atomically accumulates into g_agg.
// 64 edges per CTA, 256 threads, 4x4 register tile per thread.
// ============================================================
template <bool NODE>
__global__ __launch_bounds__(256) void edge_kernel(
    const float* __restrict__ efin,
    const int* __restrict__ src, const int* __restrict__ dst,
    const float* __restrict__ rbf, const float* __restrict__ sw,
    const float* __restrict__ W1, const float* __restrict__ b1,
    const float* __restrict__ W2, const float* __restrict__ b2,
    const float* __restrict__ gW1, const float* __restrict__ gb1,
    const float* __restrict__ gW2, const float* __restrict__ gb2,
    const float* __restrict__ wfW,
    float* __restrict__ out, int E)
{
    extern __shared__ float smbuf[];
    float* sW1  = smbuf;            // 4096
    float* sgW1 = sW1 + 4096;       // 4096
    float* sW2  = sgW1 + 4096;      // 4096
    float* sgW2 = sW2 + 4096;       // 4096
    float* sEG  = sgW2 + 4096;      // 4096 (edge features; reused for gate hidden)
    float* sH   = sEG + 4096;       // 4096
    float* sWF  = sH + 4096;        // 576
    float* sRBF = sWF + 576;        // 64*10
    float* sB1  = sRBF + 640;       // 64
    float* sGB1 = sB1 + 64;         // 64
    float* sB2  = sGB1 + 64;        // 64
    float* sGB2 = sB2 + 64;         // 64
    int* sSRC   = (int*)(sGB2 + 64);// 64
    int* sDST   = sSRC + 64;        // 64

    int tid = threadIdx.x;
    int e0 = blockIdx.x * EDGE_TILE;

    // ---- cooperative loads ----
    for (int i = tid; i < 1024; i += 256) {
        ((float4*)sW1)[i]  = ((const float4*)W1)[1024 + i];   // rows 64..127 of [192,64]
        ((float4*)sgW1)[i] = ((const float4*)gW1)[1024 + i];
        ((float4*)sW2)[i]  = ((const float4*)W2)[i];
        ((float4*)sgW2)[i] = ((const float4*)gW2)[i];
        int m = i >> 4;
        float4 v = make_float4(0.f, 0.f, 0.f, 0.f);
        if (e0 + m < E) v = ((const float4*)efin)[(size_t)(e0 + m) * 16 + (i & 15)];
        ((float4*)sEG)[i] = v;
    }
    for (int i = tid; i < 144; i += 256) ((float4*)sWF)[i] = ((const float4*)wfW)[i];
    for (int i = tid; i < 64 * 9; i += 256) {
        int m = i / 9, r = i - m * 9;
        sRBF[m * 10 + r] = (e0 + m < E) ? rbf[(size_t)(e0 + m) * 9 + r] : 0.f;
    }
    if (tid < 64) {
        sB1[tid] = b1[tid]; sGB1[tid] = gb1[tid];
        sB2[tid] = b2[tid]; sGB2[tid] = gb2[tid];
        int e = e0 + tid;
        sSRC[tid] = (e < E) ? src[e] : 0;
        sDST[tid] = (e < E) ? dst[e] : 0;
    }
    __syncthreads();

    int tx = tid & 15, ty = tid >> 4;
    int n0 = 4 * tx;
    int m_base = 4 * ty;

    const float* Pi  = g_P + (size_t)(NODE ? 4 : 0) * NN * 64;
    const float* Pj  = g_P + (size_t)(NODE ? 5 : 1) * NN * 64;
    const float* gPi = g_P + (size_t)(NODE ? 6 : 2) * NN * 64;
    const float* gPj = g_P + (size_t)(NODE ? 7 : 3) * NN * 64;

    // ---- phase 1: a1 = P_i[src] + P_j[dst] + b1 + ef @ W1_mid (h and gate) ----
    float aH[4][4], aG[4][4];
    #pragma unroll
    for (int i = 0; i < 4; i++) {
        int s = sSRC[m_base + i], d = sDST[m_base + i];
        float4 pi = *(const float4*)&Pi[(size_t)s * 64 + n0];
        float4 pj = *(const float4*)&Pj[(size_t)d * 64 + n0];
        float4 gi = *(const float4*)&gPi[(size_t)s * 64 + n0];
        float4 gj = *(const float4*)&gPj[(size_t)d * 64 + n0];
        aH[i][0] = pi.x + pj.x + sB1[n0 + 0];
        aH[i][1] = pi.y + pj.y + sB1[n0 + 1];
        aH[i][2] = pi.z + pj.z + sB1[n0 + 2];
        aH[i][3] = pi.w + pj.w + sB1[n0 + 3];
        aG[i][0] = gi.x + gj.x + sGB1[n0 + 0];
        aG[i][1] = gi.y + gj.y + sGB1[n0 + 1];
        aG[i][2] = gi.z + gj.z + sGB1[n0 + 2];
        aG[i][3] = gi.w + gj.w + sGB1[n0 + 3];
    }

    #pragma unroll 16
    for (int k = 0; k < 64; k++) {
        float a0 = sEG[(m_base + 0) * 64 + k];
        float a1 = sEG[(m_base + 1) * 64 + k];
        float a2 = sEG[(m_base + 2) * 64 + k];
        float a3 = sEG[(m_base + 3) * 64 + k];
        float4 b  = *(const float4*)&sW1[k * 64 + n0];
        float4 bg = *(const float4*)&sgW1[k * 64 + n0];
        aH[0][0] += a0 * b.x;  aH[0][1] += a0 * b.y;  aH[0][2] += a0 * b.z;  aH[0][3] += a0 * b.w;
        aH[1][0] += a1 * b.x;  aH[1][1] += a1 * b.y;  aH[1][2] += a1 * b.z;  aH[1][3] += a1 * b.w;
        aH[2][0] += a2 * b.x;  aH[2][1] += a2 * b.y;  aH[2][2] += a2 * b.z;  aH[2][3] += a2 * b.w;
        aH[3][0] += a3 * b.x;  aH[3][1] += a3 * b.y;  aH[3][2] += a3 * b.z;  aH[3][3] += a3 * b.w;
        aG[0][0] += a0 * bg.x; aG[0][1] += a0 * bg.y; aG[0][2] += a0 * bg.z; aG[0][3] += a0 * bg.w;
        aG[1][0] += a1 * bg.x; aG[1][1] += a1 * bg.y; aG[1][2] += a1 * bg.z; aG[1][3] += a1 * bg.w;
        aG[2][0] += a2 * bg.x; aG[2][1] += a2 * bg.y; aG[2][2] += a2 * bg.z; aG[2][3] += a2 * bg.w;
        aG[3][0] += a3 * bg.x; aG[3][1] += a3 * bg.y; aG[3][2] += a3 * bg.z; aG[3][3] += a3 * bg.w;
    }

    #pragma unroll
    for (int i = 0; i < 4; i++)
        #pragma unroll
        for (int j = 0; j < 4; j++) {
            aH[i][j] = silu_(aH[i][j]);
            aG[i][j] = silu_(aG[i][j]);
        }

    __syncthreads();  // everyone done reading sEG before reuse as gate-hidden
    #pragma unroll
    for (int i = 0; i < 4; i++) {
        *(float4*)&sH[(m_base + i) * 64 + n0]  = make_float4(aH[i][0], aH[i][1], aH[i][2], aH[i][3]);
        *(float4*)&sEG[(m_base + i) * 64 + n0] = make_float4(aG[i][0], aG[i][1], aG[i][2], aG[i][3]);
    }
    __syncthreads();

    // ---- phase 2: h2 = h1 @ W2 + b2 ; g2pre = g1 @ gW2 + gb2 ----
    float cH[4][4], cG[4][4];
    #pragma unroll
    for (int i = 0; i < 4; i++)
        #pragma unroll
        for (int j = 0; j < 4; j++) {
            cH[i][j] = sB2[n0 + j];
            cG[i][j] = sGB2[n0 + j];
        }

    #pragma unroll 16
    for (int k = 0; k < 64; k++) {
        float h0 = sH[(m_base + 0) * 64 + k];
        float h1 = sH[(m_base + 1) * 64 + k];
        float h2 = sH[(m_base + 2) * 64 + k];
        float h3 = sH[(m_base + 3) * 64 + k];
        float g0 = sEG[(m_base + 0) * 64 + k];
        float g1 = sEG[(m_base + 1) * 64 + k];
        float g2 = sEG[(m_base + 2) * 64 + k];
        float g3 = sEG[(m_base + 3) * 64 + k];
        float4 b  = *(const float4*)&sW2[k * 64 + n0];
        float4 bg = *(const float4*)&sgW2[k * 64 + n0];
        cH[0][0] += h0 * b.x;  cH[0][1] += h0 * b.y;  cH[0][2] += h0 * b.z;  cH[0][3] += h0 * b.w;
        cH[1][0] += h1 * b.x;  cH[1][1] += h1 * b.y;  cH[1][2] += h1 * b.z;  cH[1][3] += h1 * b.w;
        cH[2][0] += h2 * b.x;  cH[2][1] += h2 * b.y;  cH[2][2] += h2 * b.z;  cH[2][3] += h2 * b.w;
        cH[3][0] += h3 * b.x;  cH[3][1] += h3 * b.y;  cH[3][2] += h3 * b.z;  cH[3][3] += h3 * b.w;
        cG[0][0] += g0 * bg.x; cG[0][1] += g0 * bg.y; cG[0][2] += g0 * bg.z; cG[0][3] += g0 * bg.w;
        cG[1][0] += g1 * bg.x; cG[1][1] += g1 * bg.y; cG[1][2] += g1 * bg.z; cG[1][3] += g1 * bg.w;
        cG[2][0] += g2 * bg.x; cG[2][1] += g2 * bg.y; cG[2][2] += g2 * bg.z; cG[2][3] += g2 * bg.w;
        cG[3][0] += g3 * bg.x; cG[3][1] += g3 * bg.y; cG[3][2] += g3 * bg.z; cG[3][3] += g3 * bg.w;
    }

    // ---- epilogue ----
    #pragma unroll
    for (int i = 0; i < 4; i++) {
        int e = e0 + m_base + i;
        if (e >= E) continue;
        float swv[4];
        *(float4*)swv = *(const float4*)&sw[(size_t)e * 64 + n0];
        float efv[4] = {0.f, 0.f, 0.f, 0.f};
        if (!NODE) *(float4*)efv = *(const float4*)&efin[(size_t)e * 64 + n0];
        int dnode = sDST[m_base + i];
        float res[4];
        #pragma unroll
        for (int j = 0; j < 4; j++) {
            float h2 = silu_(cH[i][j]);
            float g2 = sigm_(cG[i][j]);
            float wf = 0.f;
            #pragma unroll
            for (int r = 0; r < 9; r++)
                wf += sRBF[(m_base + i) * 10 + r] * sWF[r * 64 + n0 + j];
            float val = h2 * g2 * wf * swv[j];
            if (NODE) {
                atomicAdd(&g_agg[(size_t)dnode * 64 + n0 + j], val);
            } else {
                res[j] = efv[j] + val;
            }
        }
        if (!NODE) *(float4*)&out[(size_t)e * 64 + n0] = *(float4*)res;
    }
}

// ============================================================
// Kernel D: new_node = nf + g_agg @ node_out_W
// ============================================================
__global__ __launch_bounds__(256) void nodeout_kernel(
    const float* __restrict__ nf, const float* __restrict__ Wout,
    float* __restrict__ out)
{
    __shared__ float sAG[64 * 64];
    __shared__ float sW[64 * 64];

    int tid = threadIdx.x;
    int m0 = blockIdx.x * 64;

    for (int i = tid; i < 1024; i += 256) {
        ((float4*)sW)[i] = ((const float4*)Wout)[i];
        int m = i >> 4;
        float4 v = make_float4(0.f, 0.f, 0.f, 0.f);
        if (m0 + m < NN) v = *(const float4*)&g_agg[(size_t)(m0 + m) * 64 + 4 * (i & 15)];
        ((float4*)sAG)[i] = v;
    }
    __syncthreads();

    int tx = tid & 15, ty = tid >> 4;
    int n0 = 4 * tx;
    float acc[4][4] = {};

    #pragma unroll 16
    for (int k = 0; k < 64; k++) {
        float a0 = sAG[(4 * ty + 0) * 64 + k];
        float a1 = sAG[(4 * ty + 1) * 64 + k];
        float a2 = sAG[(4 * ty + 2) * 64 + k];
        float a3 = sAG[(4 * ty + 3) * 64 + k];
        float4 b = *(const float4*)&sW[k * 64 + n0];
        acc[0][0] += a0 * b.x; acc[0][1] += a0 * b.y; acc[0][2] += a0 * b.z; acc[0][3] += a0 * b.w;
        acc[1][0] += a1 * b.x; acc[1][1] += a1 * b.y; acc[1][2] += a1 * b.z; acc[1][3] += a1 * b.w;
        acc[2][0] += a2 * b.x; acc[2][1] += a2 * b.y; acc[2][2] += a2 * b.z; acc[2][3] += a2 * b.w;
        acc[3][0] += a3 * b.x; acc[3][1] += a3 * b.y; acc[3][2] += a3 * b.z; acc[3][3] += a3 * b.w;
    }

    #pragma unroll
    for (int i = 0; i < 4; i++) {
        int m = m0 + 4 * ty + i;
        if (m < NN) {
            float4 base = *(const float4*)&nf[(size_t)m * 64 + n0];
            *(float4*)&out[(size_t)m * 64 + n0] = make_float4(
                base.x + acc[i][0], base.y + acc[i][1],
                base.z + acc[i][2], base.w + acc[i][3]);
        }
    }
}

// ============================================================
// launch
// ============================================================
extern "C" void kernel_launch(void* const* d_in, const int* in_sizes, int n_in,
                              void* d_out, int out_size) {
    const float* nf   = (const float*)d_in[0];
    const float* ef   = (const float*)d_in[1];
    const int*   src  = (const int*)d_in[2];
    const int*   dst  = (const int*)d_in[3];
    const float* rbf  = (const float*)d_in[4];
    const float* snw  = (const float*)d_in[5];
    const float* sew  = (const float*)d_in[6];
    const float* eW1  = (const float*)d_in[7];
    const float* eb1  = (const float*)d_in[8];
    const float* eW2  = (const float*)d_in[9];
    const float* eb2  = (const float*)d_in[10];
    const float* egW1 = (const float*)d_in[11];
    const float* egb1 = (const float*)d_in[12];
    const float* egW2 = (const float*)d_in[13];
    const float* egb2 = (const float*)d_in[14];
    const float* nW1  = (const float*)d_in[15];
    const float* nb1  = (const float*)d_in[16];
    const float* nW2  = (const float*)d_in[17];
    const float* nb2  = (const float*)d_in[18];
    const float* ngW1 = (const float*)d_in[19];
    const float* ngb1 = (const float*)d_in[20];
    const float* ngW2 = (const float*)d_in[21];
    const float* ngb2 = (const float*)d_in[22];
    const float* WoutM = (const float*)d_in[23];
    const float* nwf  = (const float*)d_in[24];
    const float* ewf  = (const float*)d_in[25];

    int E = in_sizes[2];

    float* outNode = (float*)d_out;
    float* outEdge = outNode + (size_t)NN * 64;

    const int SMEM_BYTES = (4096 * 6 + 576 + 640 + 256 + 128) * 4;  // 104704 B

    cudaFuncSetAttribute(edge_kernel<false>, cudaFuncAttributeMaxDynamicSharedMemorySize, SMEM_BYTES);
    cudaFuncSetAttribute(edge_kernel<true>,  cudaFuncAttributeMaxDynamicSharedMemorySize, SMEM_BYTES);

    dim3 gA((NN + 63) / 64, 8);
    proj_kernel<<<gA, THREADS>>>(nf, eW1, egW1, nW1, ngW1);

    zero_agg_kernel<<<((size_t)NN * 64 + 255) / 256, 256>>>();

    int gE = (E + EDGE_TILE - 1) / EDGE_TILE;
    edge_kernel<false><<<gE, THREADS, SMEM_BYTES>>>(
        ef, src, dst, rbf, sew,
        eW1, eb1, eW2, eb2, egW1, egb1, egW2, egb2,
        ewf, outEdge, E);

    edge_kernel<true><<<gE, THREADS, SMEM_BYTES>>>(
        outEdge, src, dst, rbf, snw,
        nW1, nb1, nW2, nb2, ngW1, ngb1, ngW2, ngb2,
        nwf, nullptr, E);

    nodeout_kernel<<<(NN + 63) / 64, THREADS>>>(nf, WoutM, outNode);
}

// round 2
// speedup vs baseline: 1.0395x; 1.0395x over previous
#include <cuda_runtime.h>

#define NN 50000
#define EDGE_TILE 64
#define THREADS 256

// ---- scratch (static device globals: allocation-free) ----
// g_P layout: slot-major, g_P[slot*NN*64 + node*64 + d]
// slots: 0 e_W1_i, 1 e_W1_j, 2 e_gW1_i, 3 e_gW1_j, 4 n_W1_i, 5 n_W1_j, 6 n_gW1_i, 7 n_gW1_j
__device__ float g_P[(size_t)8 * NN * 64];
__device__ float g_agg[(size_t)NN * 64];

__device__ __forceinline__ float sigm_(float x) { return 1.0f / (1.0f + __expf(-x)); }
__device__ __forceinline__ float silu_(float x) { return x * sigm_(x); }

// ============================================================
// Kernel A: node projections.  g_P[slot][node] = nf[node] @ Wblk
// grid: (ceil(NN/64), 8), 256 threads
// ============================================================
__global__ __launch_bounds__(256) void proj_kernel(
    const float* __restrict__ nf,
    const float* __restrict__ eW1, const float* __restrict__ egW1,
    const float* __restrict__ nW1, const float* __restrict__ ngW1)
{
    __shared__ float sNF[64 * 64];
    __shared__ float sW[64 * 64];

    int slot = blockIdx.y;
    const float* W;
    int roff;
    switch (slot) {
        case 0: W = eW1;  roff = 0;   break;
        case 1: W = eW1;  roff = 128; break;
        case 2: W = egW1; roff = 0;   break;
        case 3: W = egW1; roff = 128; break;
        case 4: W = nW1;  roff = 0;   break;
        case 5: W = nW1;  roff = 128; break;
        case 6: W = ngW1; roff = 0;   break;
        default: W = ngW1; roff = 128; break;
    }

    int tid = threadIdx.x;
    int m0 = blockIdx.x * 64;
    const float4* Wv = (const float4*)W;
    const float4* nfv = (const float4*)nf;

    for (int i = tid; i < 1024; i += 256) {
        ((float4*)sW)[i] = Wv[roff * 16 + i];
        int m = i >> 4;
        float4 v = make_float4(0.f, 0.f, 0.f, 0.f);
        if (m0 + m < NN) v = nfv[(size_t)(m0 + m) * 16 + (i & 15)];
        ((float4*)sNF)[i] = v;
    }
    __syncthreads();

    int tx = tid & 15, ty = tid >> 4;
    int n0 = 4 * tx;
    float acc[4][4] = {};

    #pragma unroll 16
    for (int k = 0; k < 64; k++) {
        float a0 = sNF[(4 * ty + 0) * 64 + k];
        float a1 = sNF[(4 * ty + 1) * 64 + k];
        float a2 = sNF[(4 * ty + 2) * 64 + k];
        float a3 = sNF[(4 * ty + 3) * 64 + k];
        float4 b = *(const float4*)&sW[k * 64 + n0];
        acc[0][0] += a0 * b.x; acc[0][1] += a0 * b.y; acc[0][2] += a0 * b.z; acc[0][3] += a0 * b.w;
        acc[1][0] += a1 * b.x; acc[1][1] += a1 * b.y; acc[1][2] += a1 * b.z; acc[1][3] += a1 * b.w;
        acc[2][0] += a2 * b.x; acc[2][1] += a2 * b.y; acc[2][2] += a2 * b.z; acc[2][3] += a2 * b.w;
        acc[3][0] += a3 * b.x; acc[3][1] += a3 * b.y; acc[3][2] += a3 * b.z; acc[3][3] += a3 * b.w;
    }

    float* outp = g_P + (size_t)slot * NN * 64;
    #pragma unroll
    for (int i = 0; i < 4; i++) {
        int m = m0 + 4 * ty + i;
        if (m < NN) {
            *(float4*)&outp[(size_t)m * 64 + n0] =
                make_float4(acc[i][0], acc[i][1], acc[i][2], acc[i][3]);
        }
    }
}

// ============================================================
// zero g_agg
// ============================================================
__global__ void zero_agg_kernel() {
    size_t i = (size_t)blockIdx.x * 256 + threadIdx.x;
    if (i < (size_t)NN * 64) g_agg[i] = 0.f;
}

// ============================================================
// Edge/message kernel.  NODE=false: edge (bond) update, writes new_edge.
// NODE=true: node message pass, atomically accumulates into g_agg.
// 64 edges per CTA, 256 threads, 4x4 register tile per thread.
// ============================================================
template <bool NODE>
__global__ __launch_bounds__(256) void edge_kernel(
    const float* __restrict__ efin,
    const int* __restrict__ src, const int* __restrict__ dst,
    const float* __restrict__ rbf, const float* __restrict__ sw,
    const float* __restrict__ W1, const float* __restrict__ b1,
    const float* __restrict__ W2, const float* __restrict__ b2,
    const float* __restrict__ gW1, const float* __restrict__ gb1,
    const float* __restrict__ gW2, const float* __restrict__ gb2,
    const float* __restrict__ wfW,
    float* __restrict__ out, int E)
{
    extern __shared__ float smbuf[];
    float* sW1  = smbuf;            // 4096
    float* sgW1 = sW1 + 4096;       // 4096
    float* sW2  = sgW1 + 4096;      // 4096
    float* sgW2 = sW2 + 4096;       // 4096
    float* sEG  = sgW2 + 4096;      // 4096 (edge features; reused for gate hidden)
    float* sH   = sEG + 4096;       // 4096
    float* sWF  = sH + 4096;        // 576
    float* sRBF = sWF + 576;        // 64*10
    float* sB1  = sRBF + 640;       // 64
    float* sGB1 = sB1 + 64;         // 64
    float* sB2  = sGB1 + 64;        // 64
    float* sGB2 = sB2 + 64;         // 64
    int* sSRC   = (int*)(sGB2 + 64);// 64
    int* sDST   = sSRC + 64;        // 64

    int tid = threadIdx.x;
    int e0 = blockIdx.x * EDGE_TILE;

    // ---- cooperative loads ----
    for (int i = tid; i < 1024; i += 256) {
        ((float4*)sW1)[i]  = ((const float4*)W1)[1024 + i];   // rows 64..127 of [192,64]
        ((float4*)sgW1)[i] = ((const float4*)gW1)[1024 + i];
        ((float4*)sW2)[i]  = ((const float4*)W2)[i];
        ((float4*)sgW2)[i] = ((const float4*)gW2)[i];
        int m = i >> 4;
        float4 v = make_float4(0.f, 0.f, 0.f, 0.f);
        if (e0 + m < E) v = ((const float4*)efin)[(size_t)(e0 + m) * 16 + (i & 15)];
        ((float4*)sEG)[i] = v;
    }
    for (int i = tid; i < 144; i += 256) ((float4*)sWF)[i] = ((const float4*)wfW)[i];
    for (int i = tid; i < 64 * 9; i += 256) {
        int m = i / 9, r = i - m * 9;
        sRBF[m * 10 + r] = (e0 + m < E) ? rbf[(size_t)(e0 + m) * 9 + r] : 0.f;
    }
    if (tid < 64) {
        sB1[tid] = b1[tid]; sGB1[tid] = gb1[tid];
        sB2[tid] = b2[tid]; sGB2[tid] = gb2[tid];
        int e = e0 + tid;
        sSRC[tid] = (e < E) ? src[e] : 0;
        sDST[tid] = (e < E) ? dst[e] : 0;
    }
    __syncthreads();

    int tx = tid & 15, ty = tid >> 4;
    int n0 = 4 * tx;
    int m_base = 4 * ty;

    const float* Pi  = g_P + (size_t)(NODE ? 4 : 0) * NN * 64;
    const float* Pj  = g_P + (size_t)(NODE ? 5 : 1) * NN * 64;
    const float* gPi = g_P + (size_t)(NODE ? 6 : 2) * NN * 64;
    const float* gPj = g_P + (size_t)(NODE ? 7 : 3) * NN * 64;

    // ---- phase 1: a1 = P_i[src] + P_j[dst] + b1 + ef @ W1_mid (h and gate) ----
    float aH[4][4], aG[4][4];
    #pragma unroll
    for (int i = 0; i < 4; i++) {
        int s = sSRC[m_base + i], d = sDST[m_base + i];
        float4 pi = *(const float4*)&Pi[(size_t)s * 64 + n0];
        float4 pj = *(const float4*)&Pj[(size_t)d * 64 + n0];
        float4 gi = *(const float4*)&gPi[(size_t)s * 64 + n0];
        float4 gj = *(const float4*)&gPj[(size_t)d * 64 + n0];
        aH[i][0] = pi.x + pj.x + sB1[n0 + 0];
        aH[i][1] = pi.y + pj.y + sB1[n0 + 1];
        aH[i][2] = pi.z + pj.z + sB1[n0 + 2];
        aH[i][3] = pi.w + pj.w + sB1[n0 + 3];
        aG[i][0] = gi.x + gj.x + sGB1[n0 + 0];
        aG[i][1] = gi.y + gj.y + sGB1[n0 + 1];
        aG[i][2] = gi.z + gj.z + sGB1[n0 + 2];
        aG[i][3] = gi.w + gj.w + sGB1[n0 + 3];
    }

    #pragma unroll 16
    for (int k = 0; k < 64; k++) {
        float a0 = sEG[(m_base + 0) * 64 + k];
        float a1 = sEG[(m_base + 1) * 64 + k];
        float a2 = sEG[(m_base + 2) * 64 + k];
        float a3 = sEG[(m_base + 3) * 64 + k];
        float4 b  = *(const float4*)&sW1[k * 64 + n0];
        float4 bg = *(const float4*)&sgW1[k * 64 + n0];
        aH[0][0] += a0 * b.x;  aH[0][1] += a0 * b.y;  aH[0][2] += a0 * b.z;  aH[0][3] += a0 * b.w;
        aH[1][0] += a1 * b.x;  aH[1][1] += a1 * b.y;  aH[1][2] += a1 * b.z;  aH[1][3] += a1 * b.w;
        aH[2][0] += a2 * b.x;  aH[2][1] += a2 * b.y;  aH[2][2] += a2 * b.z;  aH[2][3] += a2 * b.w;
        aH[3][0] += a3 * b.x;  aH[3][1] += a3 * b.y;  aH[3][2] += a3 * b.z;  aH[3][3] += a3 * b.w;
        aG[0][0] += a0 * bg.x; aG[0][1] += a0 * bg.y; aG[0][2] += a0 * bg.z; aG[0][3] += a0 * bg.w;
        aG[1][0] += a1 * bg.x; aG[1][1] += a1 * bg.y; aG[1][2] += a1 * bg.z; aG[1][3] += a1 * bg.w;
        aG[2][0] += a2 * bg.x; aG[2][1] += a2 * bg.y; aG[2][2] += a2 * bg.z; aG[2][3] += a2 * bg.w;
        aG[3][0] += a3 * bg.x; aG[3][1] += a3 * bg.y; aG[3][2] += a3 * bg.z; aG[3][3] += a3 * bg.w;
    }

    #pragma unroll
    for (int i = 0; i < 4; i++)
        #pragma unroll
        for (int j = 0; j < 4; j++) {
            aH[i][j] = silu_(aH[i][j]);
            aG[i][j] = silu_(aG[i][j]);
        }

    __syncthreads();  // everyone done reading sEG before reuse as gate-hidden
    #pragma unroll
    for (int i = 0; i < 4; i++) {
        *(float4*)&sH[(m_base + i) * 64 + n0]  = make_float4(aH[i][0], aH[i][1], aH[i][2], aH[i][3]);
        *(float4*)&sEG[(m_base + i) * 64 + n0] = make_float4(aG[i][0], aG[i][1], aG[i][2], aG[i][3]);
    }
    __syncthreads();

    // ---- phase 2: h2 = h1 @ W2 + b2 ; g2pre = g1 @ gW2 + gb2 ----
    float cH[4][4], cG[4][4];
    #pragma unroll
    for (int i = 0; i < 4; i++)
        #pragma unroll
        for (int j = 0; j < 4; j++) {
            cH[i][j] = sB2[n0 + j];
            cG[i][j] = sGB2[n0 + j];
        }

    #pragma unroll 16
    for (int k = 0; k < 64; k++) {
        float h0 = sH[(m_base + 0) * 64 + k];
        float h1 = sH[(m_base + 1) * 64 + k];
        float h2 = sH[(m_base + 2) * 64 + k];
        float h3 = sH[(m_base + 3) * 64 + k];
        float g0 = sEG[(m_base + 0) * 64 + k];
        float g1 = sEG[(m_base + 1) * 64 + k];
        float g2 = sEG[(m_base + 2) * 64 + k];
        float g3 = sEG[(m_base + 3) * 64 + k];
        float4 b  = *(const float4*)&sW2[k * 64 + n0];
        float4 bg = *(const float4*)&sgW2[k * 64 + n0];
        cH[0][0] += h0 * b.x;  cH[0][1] += h0 * b.y;  cH[0][2] += h0 * b.z;  cH[0][3] += h0 * b.w;
        cH[1][0] += h1 * b.x;  cH[1][1] += h1 * b.y;  cH[1][2] += h1 * b.z;  cH[1][3] += h1 * b.w;
        cH[2][0] += h2 * b.x;  cH[2][1] += h2 * b.y;  cH[2][2] += h2 * b.z;  cH[2][3] += h2 * b.w;
        cH[3][0] += h3 * b.x;  cH[3][1] += h3 * b.y;  cH[3][2] += h3 * b.z;  cH[3][3] += h3 * b.w;
        cG[0][0] += g0 * bg.x; cG[0][1] += g0 * bg.y; cG[0][2] += g0 * bg.z; cG[0][3] += g0 * bg.w;
        cG[1][0] += g1 * bg.x; cG[1][1] += g1 * bg.y; cG[1][2] += g1 * bg.z; cG[1][3] += g1 * bg.w;
        cG[2][0] += g2 * bg.x; cG[2][1] += g2 * bg.y; cG[2][2] += g2 * bg.z; cG[2][3] += g2 * bg.w;
        cG[3][0] += g3 * bg.x; cG[3][1] += g3 * bg.y; cG[3][2] += g3 * bg.z; cG[3][3] += g3 * bg.w;
    }

    // ---- epilogue ----
    #pragma unroll
    for (int i = 0; i < 4; i++) {
        int e = e0 + m_base + i;
        if (e >= E) continue;
        float swv[4];
        *(float4*)swv = *(const float4*)&sw[(size_t)e * 64 + n0];
        float efv[4] = {0.f, 0.f, 0.f, 0.f};
        if (!NODE) *(float4*)efv = *(const float4*)&efin[(size_t)e * 64 + n0];
        int dnode = sDST[m_base + i];
        float res[4];
        #pragma unroll
        for (int j = 0; j < 4; j++) {
            float h2 = silu_(cH[i][j]);
            float g2 = sigm_(cG[i][j]);
            float wf = 0.f;
            #pragma unroll
            for (int r = 0; r < 9; r++)
                wf += sRBF[(m_base + i) * 10 + r] * sWF[r * 64 + n0 + j];
            float val = h2 * g2 * wf * swv[j];
            if (NODE) {
                atomicAdd(&g_agg[(size_t)dnode * 64 + n0 + j], val);
            } else {
                res[j] = efv[j] + val;
            }
        }
        if (!NODE) *(float4*)&out[(size_t)e * 64 + n0] = *(float4*)res;
    }
}

// ============================================================
// Kernel D: new_node = nf + g_agg @ node_out_W
// ============================================================
__global__ __launch_bounds__(256) void nodeout_kernel(
    const float* __restrict__ nf, const float* __restrict__ Wout,
    float* __restrict__ out)
{
    __shared__ float sAG[64 * 64];
    __shared__ float sW[64 * 64];

    int tid = threadIdx.x;
    int m0 = blockIdx.x * 64;

    for (int i = tid; i < 1024; i += 256) {
        ((float4*)sW)[i] = ((const float4*)Wout)[i];
        int m = i >> 4;
        float4 v = make_float4(0.f, 0.f, 0.f, 0.f);
        if (m0 + m < NN) v = *(const float4*)&g_agg[(size_t)(m0 + m) * 64 + 4 * (i & 15)];
        ((float4*)sAG)[i] = v;
    }
    __syncthreads();

    int tx = tid & 15, ty = tid >> 4;
    int n0 = 4 * tx;
    float acc[4][4] = {};

    #pragma unroll 16
    for (int k = 0; k < 64; k++) {
        float a0 = sAG[(4 * ty + 0) * 64 + k];
        float a1 = sAG[(4 * ty + 1) * 64 + k];
        float a2 = sAG[(4 * ty + 2) * 64 + k];
        float a3 = sAG[(4 * ty + 3) * 64 + k];
        float4 b = *(const float4*)&sW[k * 64 + n0];
        acc[0][0] += a0 * b.x; acc[0][1] += a0 * b.y; acc[0][2] += a0 * b.z; acc[0][3] += a0 * b.w;
        acc[1][0] += a1 * b.x; acc[1][1] += a1 * b.y; acc[1][2] += a1 * b.z; acc[1][3] += a1 * b.w;
        acc[2][0] += a2 * b.x; acc[2][1] += a2 * b.y; acc[2][2] += a2 * b.z; acc[2][3] += a2 * b.w;
        acc[3][0] += a3 * b.x; acc[3][1] += a3 * b.y; acc[3][2] += a3 * b.z; acc[3][3] += a3 * b.w;
    }

    #pragma unroll
    for (int i = 0; i < 4; i++) {
        int m = m0 + 4 * ty + i;
        if (m < NN) {
            float4 base = *(const float4*)&nf[(size_t)m * 64 + n0];
            *(float4*)&out[(size_t)m * 64 + n0] = make_float4(
                base.x + acc[i][0], base.y + acc[i][1],
                base.z + acc[i][2], base.w + acc[i][3]);
        }
    }
}

// ============================================================
// launch
// ============================================================
extern "C" void kernel_launch(void* const* d_in, const int* in_sizes, int n_in,
                              void* d_out, int out_size) {
    const float* nf   = (const float*)d_in[0];
    const float* ef   = (const float*)d_in[1];
    const int*   src  = (const int*)d_in[2];
    const int*   dst  = (const int*)d_in[3];
    const float* rbf  = (const float*)d_in[4];
    const float* snw  = (const float*)d_in[5];
    const float* sew  = (const float*)d_in[6];
    const float* eW1  = (const float*)d_in[7];
    const float* eb1  = (const float*)d_in[8];
    const float* eW2  = (const float*)d_in[9];
    const float* eb2  = (const float*)d_in[10];
    const float* egW1 = (const float*)d_in[11];
    const float* egb1 = (const float*)d_in[12];
    const float* egW2 = (const float*)d_in[13];
    const float* egb2 = (const float*)d_in[14];
    const float* nW1  = (const float*)d_in[15];
    const float* nb1  = (const float*)d_in[16];
    const float* nW2  = (const float*)d_in[17];
    const float* nb2  = (const float*)d_in[18];
    const float* ngW1 = (const float*)d_in[19];
    const float* ngb1 = (const float*)d_in[20];
    const float* ngW2 = (const float*)d_in[21];
    const float* ngb2 = (const float*)d_in[22];
    const float* WoutM = (const float*)d_in[23];
    const float* nwf  = (const float*)d_in[24];
    const float* ewf  = (const float*)d_in[25];

    int E = in_sizes[2];

    float* outNode = (float*)d_out;
    float* outEdge = outNode + (size_t)NN * 64;

    const int SMEM_BYTES = (4096 * 6 + 576 + 640 + 256 + 128) * 4;  // 104704 B

    cudaFuncSetAttribute(edge_kernel<false>, cudaFuncAttributeMaxDynamicSharedMemorySize, SMEM_BYTES);
    cudaFuncSetAttribute(edge_kernel<true>,  cudaFuncAttributeMaxDynamicSharedMemorySize, SMEM_BYTES);

    dim3 gA((NN + 63) / 64, 8);
    proj_kernel<<<gA, THREADS>>>(nf, eW1, egW1, nW1, ngW1);

    zero_agg_kernel<<<((size_t)NN * 64 + 255) / 256, 256>>>();

    int gE = (E + EDGE_TILE - 1) / EDGE_TILE;
    edge_kernel<false><<<gE, THREADS, SMEM_BYTES>>>(
        ef, src, dst, rbf, sew,
        eW1, eb1, eW2, eb2, egW1, egb1, egW2, egb2,
        ewf, outEdge, E);

    edge_kernel<true><<<gE, THREADS, SMEM_BYTES>>>(
        outEdge, src, dst, rbf, snw,
        nW1, nb1, nW2, nb2, ngW1, ngb1, ngW2, ngb2,
        nwf, nullptr, E);

    nodeout_kernel<<<(NN + 63) / 64, THREADS>>>(nf, WoutM, outNode);
}

// round 3
// speedup vs baseline: 1.0398x; 1.0003x over previous
#include <cuda_runtime.h>

#define NN 50000
#define EDGE_TILE 64
#define THREADS 256

// ---- scratch (static device globals: allocation-free) ----
// g_P layout: slot-major, g_P[slot*NN*64 + node*64 + d]
// slots: 0 e_W1_i, 1 e_W1_j, 2 e_gW1_i, 3 e_gW1_j, 4 n_W1_i, 5 n_W1_j, 6 n_gW1_i, 7 n_gW1_j
__device__ float g_P[(size_t)8 * NN * 64];
__device__ float g_agg[(size_t)NN * 64];

__device__ __forceinline__ float sigm_(float x) { return 1.0f / (1.0f + __expf(-x)); }
__device__ __forceinline__ float silu_(float x) { return x * sigm_(x); }

// ============================================================
// Kernel A: node projections.  g_P[slot][node] = nf[node] @ Wblk
// grid: (ceil(NN/64), 8), 256 threads
// ============================================================
__global__ __launch_bounds__(256) void proj_kernel(
    const float* __restrict__ nf,
    const float* __restrict__ eW1, const float* __restrict__ egW1,
    const float* __restrict__ nW1, const float* __restrict__ ngW1)
{
    __shared__ float sNF[64 * 64];
    __shared__ float sW[64 * 64];

    int slot = blockIdx.y;
    const float* W;
    int roff;
    switch (slot) {
        case 0: W = eW1;  roff = 0;   break;
        case 1: W = eW1;  roff = 128; break;
        case 2: W = egW1; roff = 0;   break;
        case 3: W = egW1; roff = 128; break;
        case 4: W = nW1;  roff = 0;   break;
        case 5: W = nW1;  roff = 128; break;
        case 6: W = ngW1; roff = 0;   break;
        default: W = ngW1; roff = 128; break;
    }

    int tid = threadIdx.x;
    int m0 = blockIdx.x * 64;
    const float4* Wv = (const float4*)W;
    const float4* nfv = (const float4*)nf;

    for (int i = tid; i < 1024; i += 256) {
        ((float4*)sW)[i] = Wv[roff * 16 + i];
        int m = i >> 4;
        float4 v = make_float4(0.f, 0.f, 0.f, 0.f);
        if (m0 + m < NN) v = nfv[(size_t)(m0 + m) * 16 + (i & 15)];
        ((float4*)sNF)[i] = v;
    }
    __syncthreads();

    int tx = tid & 15, ty = tid >> 4;
    int n0 = 4 * tx;
    float acc[4][4] = {};

    #pragma unroll 16
    for (int k = 0; k < 64; k++) {
        float a0 = sNF[(4 * ty + 0) * 64 + k];
        float a1 = sNF[(4 * ty + 1) * 64 + k];
        float a2 = sNF[(4 * ty + 2) * 64 + k];
        float a3 = sNF[(4 * ty + 3) * 64 + k];
        float4 b = *(const float4*)&sW[k * 64 + n0];
        acc[0][0] += a0 * b.x; acc[0][1] += a0 * b.y; acc[0][2] += a0 * b.z; acc[0][3] += a0 * b.w;
        acc[1][0] += a1 * b.x; acc[1][1] += a1 * b.y; acc[1][2] += a1 * b.z; acc[1][3] += a1 * b.w;
        acc[2][0] += a2 * b.x; acc[2][1] += a2 * b.y; acc[2][2] += a2 * b.z; acc[2][3] += a2 * b.w;
        acc[3][0] += a3 * b.x; acc[3][1] += a3 * b.y; acc[3][2] += a3 * b.z; acc[3][3] += a3 * b.w;
    }

    float* outp = g_P + (size_t)slot * NN * 64;
    #pragma unroll
    for (int i = 0; i < 4; i++) {
        int m = m0 + 4 * ty + i;
        if (m < NN) {
            *(float4*)&outp[(size_t)m * 64 + n0] =
                make_float4(acc[i][0], acc[i][1], acc[i][2], acc[i][3]);
        }
    }
}

// ============================================================
// zero g_agg
// ============================================================
__global__ void zero_agg_kernel() {
    size_t i = (size_t)blockIdx.x * 256 + threadIdx.x;
    if (i < (size_t)NN * 64) g_agg[i] = 0.f;
}

// ============================================================
// Edge/message kernel.  NODE=false: edge (bond) update, writes new_edge.
// NODE=true: node message pass, atomically accumulates into g_agg.
// 64 edges per CTA, 256 threads, 4x4 register tile per thread.
// ============================================================
template <bool NODE>
__global__ __launch_bounds__(256) void edge_kernel(
    const float* __restrict__ efin,
    const int* __restrict__ src, const int* __restrict__ dst,
    const float* __restrict__ rbf, const float* __restrict__ sw,
    const float* __restrict__ W1, const float* __restrict__ b1,
    const float* __restrict__ W2, const float* __restrict__ b2,
    const float* __restrict__ gW1, const float* __restrict__ gb1,
    const float* __restrict__ gW2, const float* __restrict__ gb2,
    const float* __restrict__ wfW,
    float* __restrict__ out, int E)
{
    extern __shared__ float smbuf[];
    float* sW1  = smbuf;            // 4096
    float* sgW1 = sW1 + 4096;       // 4096
    float* sW2  = sgW1 + 4096;      // 4096
    float* sgW2 = sW2 + 4096;       // 4096
    float* sEG  = sgW2 + 4096;      // 4096 (edge features; reused for gate hidden)
    float* sH   = sEG + 4096;       // 4096
    float* sWF  = sH + 4096;        // 576
    float* sRBF = sWF + 576;        // 64*10
    float* sB1  = sRBF + 640;       // 64
    float* sGB1 = sB1 + 64;         // 64
    float* sB2  = sGB1 + 64;        // 64
    float* sGB2 = sB2 + 64;         // 64
    int* sSRC   = (int*)(sGB2 + 64);// 64
    int* sDST   = sSRC + 64;        // 64

    int tid = threadIdx.x;
    int e0 = blockIdx.x * EDGE_TILE;

    // ---- cooperative loads ----
    for (int i = tid; i < 1024; i += 256) {
        ((float4*)sW1)[i]  = ((const float4*)W1)[1024 + i];   // rows 64..127 of [192,64]
        ((float4*)sgW1)[i] = ((const float4*)gW1)[1024 + i];
        ((float4*)sW2)[i]  = ((const float4*)W2)[i];
        ((float4*)sgW2)[i] = ((const float4*)gW2)[i];
        int m = i >> 4;
        float4 v = make_float4(0.f, 0.f, 0.f, 0.f);
        if (e0 + m < E) v = ((const float4*)efin)[(size_t)(e0 + m) * 16 + (i & 15)];
        ((float4*)sEG)[i] = v;
    }
    for (int i = tid; i < 144; i += 256) ((float4*)sWF)[i] = ((const float4*)wfW)[i];
    for (int i = tid; i < 64 * 9; i += 256) {
        int m = i / 9, r = i - m * 9;
        sRBF[m * 10 + r] = (e0 + m < E) ? rbf[(size_t)(e0 + m) * 9 + r] : 0.f;
    }
    if (tid < 64) {
        sB1[tid] = b1[tid]; sGB1[tid] = gb1[tid];
        sB2[tid] = b2[tid]; sGB2[tid] = gb2[tid];
        int e = e0 + tid;
        sSRC[tid] = (e < E) ? src[e] : 0;
        sDST[tid] = (e < E) ? dst[e] : 0;
    }
    __syncthreads();

    int tx = tid & 15, ty = tid >> 4;
    int n0 = 4 * tx;
    int m_base = 4 * ty;

    const float* Pi  = g_P + (size_t)(NODE ? 4 : 0) * NN * 64;
    const float* Pj  = g_P + (size_t)(NODE ? 5 : 1) * NN * 64;
    const float* gPi = g_P + (size_t)(NODE ? 6 : 2) * NN * 64;
    const float* gPj = g_P + (size_t)(NODE ? 7 : 3) * NN * 64;

    // ---- phase 1: a1 = P_i[src] + P_j[dst] + b1 + ef @ W1_mid (h and gate) ----
    float aH[4][4], aG[4][4];
    #pragma unroll
    for (int i = 0; i < 4; i++) {
        int s = sSRC[m_base + i], d = sDST[m_base + i];
        float4 pi = *(const float4*)&Pi[(size_t)s * 64 + n0];
        float4 pj = *(const float4*)&Pj[(size_t)d * 64 + n0];
        float4 gi = *(const float4*)&gPi[(size_t)s * 64 + n0];
        float4 gj = *(const float4*)&gPj[(size_t)d * 64 + n0];
        aH[i][0] = pi.x + pj.x + sB1[n0 + 0];
        aH[i][1] = pi.y + pj.y + sB1[n0 + 1];
        aH[i][2] = pi.z + pj.z + sB1[n0 + 2];
        aH[i][3] = pi.w + pj.w + sB1[n0 + 3];
        aG[i][0] = gi.x + gj.x + sGB1[n0 + 0];
        aG[i][1] = gi.y + gj.y + sGB1[n0 + 1];
        aG[i][2] = gi.z + gj.z + sGB1[n0 + 2];
        aG[i][3] = gi.w + gj.w + sGB1[n0 + 3];
    }

    #pragma unroll 16
    for (int k = 0; k < 64; k++) {
        float a0 = sEG[(m_base + 0) * 64 + k];
        float a1 = sEG[(m_base + 1) * 64 + k];
        float a2 = sEG[(m_base + 2) * 64 + k];
        float a3 = sEG[(m_base + 3) * 64 + k];
        float4 b  = *(const float4*)&sW1[k * 64 + n0];
        float4 bg = *(const float4*)&sgW1[k * 64 + n0];
        aH[0][0] += a0 * b.x;  aH[0][1] += a0 * b.y;  aH[0][2] += a0 * b.z;  aH[0][3] += a0 * b.w;
        aH[1][0] += a1 * b.x;  aH[1][1] += a1 * b.y;  aH[1][2] += a1 * b.z;  aH[1][3] += a1 * b.w;
        aH[2][0] += a2 * b.x;  aH[2][1] += a2 * b.y;  aH[2][2] += a2 * b.z;  aH[2][3] += a2 * b.w;
        aH[3][0] += a3 * b.x;  aH[3][1] += a3 * b.y;  aH[3][2] += a3 * b.z;  aH[3][3] += a3 * b.w;
        aG[0][0] += a0 * bg.x; aG[0][1] += a0 * bg.y; aG[0][2] += a0 * bg.z; aG[0][3] += a0 * bg.w;
        aG[1][0] += a1 * bg.x; aG[1][1] += a1 * bg.y; aG[1][2] += a1 * bg.z; aG[1][3] += a1 * bg.w;
        aG[2][0] += a2 * bg.x; aG[2][1] += a2 * bg.y; aG[2][2] += a2 * bg.z; aG[2][3] += a2 * bg.w;
        aG[3][0] += a3 * bg.x; aG[3][1] += a3 * bg.y; aG[3][2] += a3 * bg.z; aG[3][3] += a3 * bg.w;
    }

    #pragma unroll
    for (int i = 0; i < 4; i++)
        #pragma unroll
        for (int j = 0; j < 4; j++) {
            aH[i][j] = silu_(aH[i][j]);
            aG[i][j] = silu_(aG[i][j]);
        }

    __syncthreads();  // everyone done reading sEG before reuse as gate-hidden
    #pragma unroll
    for (int i = 0; i < 4; i++) {
        *(float4*)&sH[(m_base + i) * 64 + n0]  = make_float4(aH[i][0], aH[i][1], aH[i][2], aH[i][3]);
        *(float4*)&sEG[(m_base + i) * 64 + n0] = make_float4(aG[i][0], aG[i][1], aG[i][2], aG[i][3]);
    }
    __syncthreads();

    // ---- phase 2: h2 = h1 @ W2 + b2 ; g2pre = g1 @ gW2 + gb2 ----
    float cH[4][4], cG[4][4];
    #pragma unroll
    for (int i = 0; i < 4; i++)
        #pragma unroll
        for (int j = 0; j < 4; j++) {
            cH[i][j] = sB2[n0 + j];
            cG[i][j] = sGB2[n0 + j];
        }

    #pragma unroll 16
    for (int k = 0; k < 64; k++) {
        float h0 = sH[(m_base + 0) * 64 + k];
        float h1 = sH[(m_base + 1) * 64 + k];
        float h2 = sH[(m_base + 2) * 64 + k];
        float h3 = sH[(m_base + 3) * 64 + k];
        float g0 = sEG[(m_base + 0) * 64 + k];
        float g1 = sEG[(m_base + 1) * 64 + k];
        float g2 = sEG[(m_base + 2) * 64 + k];
        float g3 = sEG[(m_base + 3) * 64 + k];
        float4 b  = *(const float4*)&sW2[k * 64 + n0];
        float4 bg = *(const float4*)&sgW2[k * 64 + n0];
        cH[0][0] += h0 * b.x;  cH[0][1] += h0 * b.y;  cH[0][2] += h0 * b.z;  cH[0][3] += h0 * b.w;
        cH[1][0] += h1 * b.x;  cH[1][1] += h1 * b.y;  cH[1][2] += h1 * b.z;  cH[1][3] += h1 * b.w;
        cH[2][0] += h2 * b.x;  cH[2][1] += h2 * b.y;  cH[2][2] += h2 * b.z;  cH[2][3] += h2 * b.w;
        cH[3][0] += h3 * b.x;  cH[3][1] += h3 * b.y;  cH[3][2] += h3 * b.z;  cH[3][3] += h3 * b.w;
        cG[0][0] += g0 * bg.x; cG[0][1] += g0 * bg.y; cG[0][2] += g0 * bg.z; cG[0][3] += g0 * bg.w;
        cG[1][0] += g1 * bg.x; cG[1][1] += g1 * bg.y; cG[1][2] += g1 * bg.z; cG[1][3] += g1 * bg.w;
        cG[2][0] += g2 * bg.x; cG[2][1] += g2 * bg.y; cG[2][2] += g2 * bg.z; cG[2][3] += g2 * bg.w;
        cG[3][0] += g3 * bg.x; cG[3][1] += g3 * bg.y; cG[3][2] += g3 * bg.z; cG[3][3] += g3 * bg.w;
    }

    // ---- epilogue ----
    #pragma unroll
    for (int i = 0; i < 4; i++) {
        int e = e0 + m_base + i;
        if (e >= E) continue;
        float swv[4];
        *(float4*)swv = *(const float4*)&sw[(size_t)e * 64 + n0];
        float efv[4] = {0.f, 0.f, 0.f, 0.f};
        if (!NODE) *(float4*)efv = *(const float4*)&efin[(size_t)e * 64 + n0];
        int dnode = sDST[m_base + i];
        float res[4];
        #pragma unroll
        for (int j = 0; j < 4; j++) {
            float h2 = silu_(cH[i][j]);
            float g2 = sigm_(cG[i][j]);
            float wf = 0.f;
            #pragma unroll
            for (int r = 0; r < 9; r++)
                wf += sRBF[(m_base + i) * 10 + r] * sWF[r * 64 + n0 + j];
            float val = h2 * g2 * wf * swv[j];
            if (NODE) {
                atomicAdd(&g_agg[(size_t)dnode * 64 + n0 + j], val);
            } else {
                res[j] = efv[j] + val;
            }
        }
        if (!NODE) *(float4*)&out[(size_t)e * 64 + n0] = *(float4*)res;
    }
}

// ============================================================
// Kernel D: new_node = nf + g_agg @ node_out_W
// ============================================================
__global__ __launch_bounds__(256) void nodeout_kernel(
    const float* __restrict__ nf, const float* __restrict__ Wout,
    float* __restrict__ out)
{
    __shared__ float sAG[64 * 64];
    __shared__ float sW[64 * 64];

    int tid = threadIdx.x;
    int m0 = blockIdx.x * 64;

    for (int i = tid; i < 1024; i += 256) {
        ((float4*)sW)[i] = ((const float4*)Wout)[i];
        int m = i >> 4;
        float4 v = make_float4(0.f, 0.f, 0.f, 0.f);
        if (m0 + m < NN) v = *(const float4*)&g_agg[(size_t)(m0 + m) * 64 + 4 * (i & 15)];
        ((float4*)sAG)[i] = v;
    }
    __syncthreads();

    int tx = tid & 15, ty = tid >> 4;
    int n0 = 4 * tx;
    float acc[4][4] = {};

    #pragma unroll 16
    for (int k = 0; k < 64; k++) {
        float a0 = sAG[(4 * ty + 0) * 64 + k];
        float a1 = sAG[(4 * ty + 1) * 64 + k];
        float a2 = sAG[(4 * ty + 2) * 64 + k];
        float a3 = sAG[(4 * ty + 3) * 64 + k];
        float4 b = *(const float4*)&sW[k * 64 + n0];
        acc[0][0] += a0 * b.x; acc[0][1] += a0 * b.y; acc[0][2] += a0 * b.z; acc[0][3] += a0 * b.w;
        acc[1][0] += a1 * b.x; acc[1][1] += a1 * b.y; acc[1][2] += a1 * b.z; acc[1][3] += a1 * b.w;
        acc[2][0] += a2 * b.x; acc[2][1] += a2 * b.y; acc[2][2] += a2 * b.z; acc[2][3] += a2 * b.w;
        acc[3][0] += a3 * b.x; acc[3][1] += a3 * b.y; acc[3][2] += a3 * b.z; acc[3][3] += a3 * b.w;
    }

    #pragma unroll
    for (int i = 0; i < 4; i++) {
        int m = m0 + 4 * ty + i;
        if (m < NN) {
            float4 base = *(const float4*)&nf[(size_t)m * 64 + n0];
            *(float4*)&out[(size_t)m * 64 + n0] = make_float4(
                base.x + acc[i][0], base.y + acc[i][1],
                base.z + acc[i][2], base.w + acc[i][3]);
        }
    }
}

// ============================================================
// launch
// ============================================================
extern "C" void kernel_launch(void* const* d_in, const int* in_sizes, int n_in,
                              void* d_out, int out_size) {
    const float* nf   = (const float*)d_in[0];
    const float* ef   = (const float*)d_in[1];
    const int*   src  = (const int*)d_in[2];
    const int*   dst  = (const int*)d_in[3];
    const float* rbf  = (const float*)d_in[4];
    const float* snw  = (const float*)d_in[5];
    const float* sew  = (const float*)d_in[6];
    const float* eW1  = (const float*)d_in[7];
    const float* eb1  = (const float*)d_in[8];
    const float* eW2  = (const float*)d_in[9];
    const float* eb2  = (const float*)d_in[10];
    const float* egW1 = (const float*)d_in[11];
    const float* egb1 = (const float*)d_in[12];
    const float* egW2 = (const float*)d_in[13];
    const float* egb2 = (const float*)d_in[14];
    const float* nW1  = (const float*)d_in[15];
    const float* nb1  = (const float*)d_in[16];
    const float* nW2  = (const float*)d_in[17];
    const float* nb2  = (const float*)d_in[18];
    const float* ngW1 = (const float*)d_in[19];
    const float* ngb1 = (const float*)d_in[20];
    const float* ngW2 = (const float*)d_in[21];
    const float* ngb2 = (const float*)d_in[22];
    const float* WoutM = (const float*)d_in[23];
    const float* nwf  = (const float*)d_in[24];
    const float* ewf  = (const float*)d_in[25];

    int E = in_sizes[2];

    float* outNode = (float*)d_out;
    float* outEdge = outNode + (size_t)NN * 64;

    const int SMEM_BYTES = (4096 * 6 + 576 + 640 + 256 + 128) * 4;  // 104704 B

    cudaFuncSetAttribute(edge_kernel<false>, cudaFuncAttributeMaxDynamicSharedMemorySize, SMEM_BYTES);
    cudaFuncSetAttribute(edge_kernel<true>,  cudaFuncAttributeMaxDynamicSharedMemorySize, SMEM_BYTES);

    dim3 gA((NN + 63) / 64, 8);
    proj_kernel<<<gA, THREADS>>>(nf, eW1, egW1, nW1, ngW1);

    zero_agg_kernel<<<((size_t)NN * 64 + 255) / 256, 256>>>();

    int gE = (E + EDGE_TILE - 1) / EDGE_TILE;
    edge_kernel<false><<<gE, THREADS, SMEM_BYTES>>>(
        ef, src, dst, rbf, sew,
        eW1, eb1, eW2, eb2, egW1, egb1, egW2, egb2,
        ewf, outEdge, E);

    edge_kernel<true><<<gE, THREADS, SMEM_BYTES>>>(
        outEdge, src, dst, rbf, snw,
        nW1, nb1, nW2, nb2, ngW1, ngb1, ngW2, ngb2,
        nwf, nullptr, E);

    nodeout_kernel<<<(NN + 63) / 64, THREADS>>>(nf, WoutM, outNode);
}

// round 7
// speedup vs baseline: 1.4694x; 1.4132x over previous
#include <cuda_runtime.h>

#define NN 50000

__device__ float g_P[(size_t)8 * NN * 64];
__device__ float g_agg[(size_t)NN * 64];

__device__ __forceinline__ float sigm_(float x) { return __fdividef(1.f, 1.f + __expf(-x)); }
__device__ __forceinline__ float silu_(float x) { return x * sigm_(x); }
__device__ __forceinline__ float tf32r(float x) {
    float y; asm("cvt.rna.tf32.f32 %0, %1;" : "=f"(y) : "f"(x)); return y;
}

// m16n8k8 tf32 HMMA, D += A*B (C==D)
__device__ __forceinline__ void mma8(float* d, const unsigned* a, const unsigned* b) {
    asm volatile("mma.sync.aligned.m16n8k8.row.col.f32.tf32.tf32.f32 "
        "{%0,%1,%2,%3},{%4,%5,%6,%7},{%8,%9},{%0,%1,%2,%3};"
        : "+f"(d[0]), "+f"(d[1]), "+f"(d[2]), "+f"(d[3])
        : "r"(a[0]), "r"(a[1]), "r"(a[2]), "r"(a[3]), "r"(b[0]), "r"(b[1]));
}

// ==================== projection kernel ====================
// grid (ceil(NN/128), 4); group g -> slots 2g (W rows 0..63) and 2g+1 (W rows 128..191)
__global__ __launch_bounds__(256) void proj_mma_kernel(
    const float* __restrict__ nf, const float* __restrict__ eW1,
    const float* __restrict__ egW1, const float* __restrict__ nW1,
    const float* __restrict__ ngW1)
{
    extern __shared__ float sm[];
    float* sB = sm;           // 64 x 136 = 8704
    float* sA = sm + 8704;    // 128 x 68 = 8704

    int tid = threadIdx.x;
    int g = blockIdx.y;
    const float* W = (g == 0) ? eW1 : (g == 1) ? egW1 : (g == 2) ? nW1 : ngW1;
    int m0 = blockIdx.x * 128;

    for (int i = tid; i < 64 * 128; i += 256) {
        int k = i >> 7, n = i & 127;
        float v = (n < 64) ? W[k * 64 + n] : W[(128 + k) * 64 + (n - 64)];
        sB[k * 136 + n] = tf32r(v);
    }
    for (int i = tid; i < 128 * 64; i += 256) {
        int m = i >> 6, k = i & 63;
        int node = m0 + m;
        sA[m * 68 + k] = tf32r(node < NN ? nf[(size_t)node * 64 + k] : 0.f);
    }
    __syncthreads();

    int lane = tid & 31, w = tid >> 5, gid = lane >> 2, tig = lane & 3;
    int r0 = 16 * w + gid, r1 = r0 + 8;

    float acc[16][4];
    #pragma unroll
    for (int nt = 0; nt < 16; nt++)
        acc[nt][0] = acc[nt][1] = acc[nt][2] = acc[nt][3] = 0.f;

    #pragma unroll 2
    for (int kt = 0; kt < 8; kt++) {
        int k0 = kt * 8;
        unsigned a[4];
        a[0] = __float_as_uint(sA[r0 * 68 + k0 + tig]);
        a[1] = __float_as_uint(sA[r1 * 68 + k0 + tig]);
        a[2] = __float_as_uint(sA[r0 * 68 + k0 + tig + 4]);
        a[3] = __float_as_uint(sA[r1 * 68 + k0 + tig + 4]);
        const float* bp0 = sB + (k0 + tig) * 136 + gid;
        const float* bp1 = bp0 + 4 * 136;
        #pragma unroll
        for (int nt = 0; nt < 16; nt++) {
            unsigned b[2] = { __float_as_uint(bp0[8 * nt]), __float_as_uint(bp1[8 * nt]) };
            mma8(acc[nt], a, b);
        }
    }

    int n0g = m0 + r0, n1g = m0 + r1;
    #pragma unroll
    for (int nt = 0; nt < 16; nt++) {
        int slot = 2 * g + (nt >> 3);
        int c = ((nt & 7) << 3) + 2 * tig;
        float* base = g_P + (size_t)slot * NN * 64;
        if (n0g < NN) *(float2*)(base + (size_t)n0g * 64 + c) = make_float2(acc[nt][0], acc[nt][1]);
        if (n1g < NN) *(float2*)(base + (size_t)n1g * 64 + c) = make_float2(acc[nt][2], acc[nt][3]);
    }
}

__global__ void zero_agg_kernel() {
    size_t i = (size_t)blockIdx.x * 256 + threadIdx.x;
    if (i < (size_t)NN * 64) g_agg[i] = 0.f;
}

// ==================== edge kernel (HMMA tf32) ====================
// 128 edges/CTA, 256 threads (8 warps), warp owns rows 16w..16w+15.
template <bool NODE>
__global__ __launch_bounds__(256) void edge_mma_kernel(
    const float* __restrict__ efin, const int* __restrict__ src,
    const int* __restrict__ dst, const float* __restrict__ rbf,
    const float* __restrict__ sw,
    const float* __restrict__ W1, const float* __restrict__ b1,
    const float* __restrict__ W2, const float* __restrict__ b2,
    const float* __restrict__ gW1, const float* __restrict__ gb1,
    const float* __restrict__ gW2, const float* __restrict__ gb2,
    const float* __restrict__ wfW, float* __restrict__ out, int E)
{
    extern __shared__ float sm[];
    float* sB1  = sm;             // 64x136 = 8704 (phase1 W; reused as Ag 128x68)
    float* sB2  = sm + 8704;      // 8704 (phase2 W: h cols 0..63, g cols 64..127)
    float* sA   = sm + 17408;     // 128x68 = 8704 (ef -> Ah)
    float* sWF  = sm + 26112;     // 576
    float* sRBF = sm + 26688;     // 1280 (128 x 10)
    float* sC1  = sm + 27968;     // 128: b1 || gb1
    float* sC2  = sm + 28096;     // 128: b2 || gb2
    int* sSRC   = (int*)(sm + 28224); // 128
    int* sDST   = (int*)(sm + 28352); // 128
    // total 28480 floats = 113920 B

    int tid = threadIdx.x;
    int e0 = blockIdx.x * 128;

    for (int i = tid; i < 64 * 128; i += 256) {
        int k = i >> 7, n = i & 127;
        float v1 = (n < 64) ? W1[(64 + k) * 64 + n] : gW1[(64 + k) * 64 + (n - 64)];
        sB1[k * 136 + n] = tf32r(v1);
        float v2 = (n < 64) ? W2[k * 64 + n] : gW2[k * 64 + (n - 64)];
        sB2[k * 136 + n] = tf32r(v2);
    }
    for (int i = tid; i < 128 * 64; i += 256) {
        int m = i >> 6, k = i & 63;
        int e = e0 + m;
        sA[m * 68 + k] = tf32r(e < E ? efin[(size_t)e * 64 + k] : 0.f);
    }
    for (int i = tid; i < 576; i += 256) sWF[i] = wfW[i];
    for (int i = tid; i < 128 * 9; i += 256) {
        int m = i / 9, r = i - 9 * m;
        int e = e0 + m;
        sRBF[m * 10 + r] = (e < E) ? rbf[(size_t)e * 9 + r] : 0.f;
    }
    if (tid < 64) {
        sC1[tid] = b1[tid]; sC1[64 + tid] = gb1[tid];
        sC2[tid] = b2[tid]; sC2[64 + tid] = gb2[tid];
    }
    if (tid < 128) {
        int e = e0 + tid;
        sSRC[tid] = (e < E) ? src[e] : 0;
        sDST[tid] = (e < E) ? dst[e] : 0;
    }
    __syncthreads();

    int lane = tid & 31, w = tid >> 5, gid = lane >> 2, tig = lane & 3;
    int r0 = 16 * w + gid, r1 = r0 + 8;
    int s0 = sSRC[r0], s1 = sSRC[r1], d0 = sDST[r0], d1 = sDST[r1];

    const float* Pi  = g_P + (size_t)(NODE ? 4 : 0) * NN * 64;
    const float* Pj  = g_P + (size_t)(NODE ? 5 : 1) * NN * 64;
    const float* gPi = g_P + (size_t)(NODE ? 6 : 2) * NN * 64;
    const float* gPj = g_P + (size_t)(NODE ? 7 : 3) * NN * 64;

    // ---- phase1 C-init = Pi[s] + Pj[d] + b1 (fp32) ----
    float acc[16][4];
    #pragma unroll
    for (int nt = 0; nt < 16; nt++) {
        int c = ((nt & 7) << 3) + 2 * tig;
        const float* Ai = (nt < 8) ? Pi : gPi;
        const float* Aj = (nt < 8) ? Pj : gPj;
        const float* bb = (nt < 8) ? sC1 : (sC1 + 64);
        float2 i0 = *(const float2*)(Ai + (size_t)s0 * 64 + c);
        float2 j0 = *(const float2*)(Aj + (size_t)d0 * 64 + c);
        float2 i1 = *(const float2*)(Ai + (size_t)s1 * 64 + c);
        float2 j1 = *(const float2*)(Aj + (size_t)d1 * 64 + c);
        float bx = bb[c], by = bb[c + 1];
        acc[nt][0] = i0.x + j0.x + bx; acc[nt][1] = i0.y + j0.y + by;
        acc[nt][2] = i1.x + j1.x + bx; acc[nt][3] = i1.y + j1.y + by;
    }

    // ---- phase1 MMA: += ef @ W1mid (h||g) ----
    #pragma unroll 2
    for (int kt = 0; kt < 8; kt++) {
        int k0 = kt * 8;
        unsigned a[4];
        a[0] = __float_as_uint(sA[r0 * 68 + k0 + tig]);
        a[1] = __float_as_uint(sA[r1 * 68 + k0 + tig]);
        a[2] = __float_as_uint(sA[r0 * 68 + k0 + tig + 4]);
        a[3] = __float_as_uint(sA[r1 * 68 + k0 + tig + 4]);
        const float* bp0 = sB1 + (k0 + tig) * 136 + gid;
        const float* bp1 = bp0 + 4 * 136;
        #pragma unroll
        for (int nt = 0; nt < 16; nt++) {
            unsigned b[2] = { __float_as_uint(bp0[8 * nt]), __float_as_uint(bp1[8 * nt]) };
            mma8(acc[nt], a, b);
        }
    }

    __syncthreads();   // all warps done reading sB1 before reuse as Ag
    float* sAg = sB1;  // 128x68 fits exactly in 8704

    // ---- silu -> Ah (sA) and Ag (sAg), tf32 ----
    #pragma unroll
    for (int nt = 0; nt < 16; nt++) {
        float* dp = (nt < 8) ? sA : sAg;
        int cc = ((nt & 7) << 3) + 2 * tig;
        *(float2*)(dp + r0 * 68 + cc) =
            make_float2(tf32r(silu_(acc[nt][0])), tf32r(silu_(acc[nt][1])));
        *(float2*)(dp + r1 * 68 + cc) =
            make_float2(tf32r(silu_(acc[nt][2])), tf32r(silu_(acc[nt][3])));
        acc[nt][0] = acc[nt][1] = acc[nt][2] = acc[nt][3] = 0.f;
    }
    __syncwarp();

    // ---- phase2 MMA: h2 = Ah @ W2 (nt<8), g2 = Ag @ gW2 (nt>=8) ----
    #pragma unroll 2
    for (int kt = 0; kt < 8; kt++) {
        int k0 = kt * 8;
        unsigned ah[4], ag[4];
        ah[0] = __float_as_uint(sA[r0 * 68 + k0 + tig]);
        ah[1] = __float_as_uint(sA[r1 * 68 + k0 + tig]);
        ah[2] = __float_as_uint(sA[r0 * 68 + k0 + tig + 4]);
        ah[3] = __float_as_uint(sA[r1 * 68 + k0 + tig + 4]);
        ag[0] = __float_as_uint(sAg[r0 * 68 + k0 + tig]);
        ag[1] = __float_as_uint(sAg[r1 * 68 + k0 + tig]);
        ag[2] = __float_as_uint(sAg[r0 * 68 + k0 + tig + 4]);
        ag[3] = __float_as_uint(sAg[r1 * 68 + k0 + tig + 4]);
        const float* bp0 = sB2 + (k0 + tig) * 136 + gid;
        const float* bp1 = bp0 + 4 * 136;
        #pragma unroll
        for (int nt = 0; nt < 16; nt++) {
            unsigned b[2] = { __float_as_uint(bp0[8 * nt]), __float_as_uint(bp1[8 * nt]) };
            mma8(acc[nt], (nt < 8) ? ah : ag, b);
        }
    }

    // ---- epilogue ----
    float rb0[9], rb1[9];
    #pragma unroll
    for (int r = 0; r < 9; r++) { rb0[r] = sRBF[r0 * 10 + r]; rb1[r] = sRBF[r1 * 10 + r]; }
    size_t eg0 = (size_t)e0 + r0, eg1 = (size_t)e0 + r1;
    bool v0 = eg0 < (size_t)E, v1 = eg1 < (size_t)E;

    #pragma unroll
    for (int nt = 0; nt < 8; nt++) {
        int c = 8 * nt + 2 * tig;
        float b2x = sC2[c], b2y = sC2[c + 1];
        float gbx = sC2[64 + c], gby = sC2[64 + c + 1];
        float h00 = silu_(acc[nt][0] + b2x), h01 = silu_(acc[nt][1] + b2y);
        float h10 = silu_(acc[nt][2] + b2x), h11 = silu_(acc[nt][3] + b2y);
        float g00 = sigm_(acc[nt + 8][0] + gbx), g01 = sigm_(acc[nt + 8][1] + gby);
        float g10 = sigm_(acc[nt + 8][2] + gbx), g11 = sigm_(acc[nt + 8][3] + gby);
        float wf00 = 0.f, wf01 = 0.f, wf10 = 0.f, wf11 = 0.f;
        #pragma unroll
        for (int r = 0; r < 9; r++) {
            float2 wv = *(const float2*)(sWF + r * 64 + c);
            wf00 += rb0[r] * wv.x; wf01 += rb0[r] * wv.y;
            wf10 += rb1[r] * wv.x; wf11 += rb1[r] * wv.y;
        }
        if (v0) {
            float2 swv = *(const float2*)(sw + eg0 * 64 + c);
            float m0 = h00 * g00 * wf00 * swv.x, m1 = h01 * g01 * wf01 * swv.y;
            if (NODE) {
                atomicAdd(&g_agg[(size_t)d0 * 64 + c], m0);
                atomicAdd(&g_agg[(size_t)d0 * 64 + c + 1], m1);
            } else {
                float2 ev = *(const float2*)(efin + eg0 * 64 + c);
                *(float2*)(out + eg0 * 64 + c) = make_float2(ev.x + m0, ev.y + m1);
            }
        }
        if (v1) {
            float2 swv = *(const float2*)(sw + eg1 * 64 + c);
            float m0 = h10 * g10 * wf10 * swv.x, m1 = h11 * g11 * wf11 * swv.y;
            if (NODE) {
                atomicAdd(&g_agg[(size_t)d1 * 64 + c], m0);
                atomicAdd(&g_agg[(size_t)d1 * 64 + c + 1], m1);
            } else {
                float2 ev = *(const float2*)(efin + eg1 * 64 + c);
                *(float2*)(out + eg1 * 64 + c) = make_float2(ev.x + m0, ev.y + m1);
            }
        }
    }
}

// ==================== node output (FFMA, small) ====================
__global__ __launch_bounds__(256) void nodeout_kernel(
    const float* __restrict__ nf, const float* __restrict__ Wout,
    float* __restrict__ out)
{
    __shared__ float sAG[4096];
    __shared__ float sW[4096];
    int tid = threadIdx.x;
    int m0 = blockIdx.x * 64;
    for (int i = tid; i < 1024; i += 256) {
        ((float4*)sW)[i] = ((const float4*)Wout)[i];
        int m = i >> 4;
        float4 v = make_float4(0.f, 0.f, 0.f, 0.f);
        if (m0 + m < NN) v = *(const float4*)&g_agg[(size_t)(m0 + m) * 64 + 4 * (i & 15)];
        ((float4*)sAG)[i] = v;
    }
    __syncthreads();
    int tx = tid & 15, ty = tid >> 4, n0 = 4 * tx;
    float acc[4][4] = {};
    #pragma unroll 16
    for (int k = 0; k < 64; k++) {
        float a0 = sAG[(4*ty+0)*64+k], a1 = sAG[(4*ty+1)*64+k];
        float a2 = sAG[(4*ty+2)*64+k], a3 = sAG[(4*ty+3)*64+k];
        float4 b = *(const float4*)&sW[k * 64 + n0];
        acc[0][0]+=a0*b.x; acc[0][1]+=a0*b.y; acc[0][2]+=a0*b.z; acc[0][3]+=a0*b.w;
        acc[1][0]+=a1*b.x; acc[1][1]+=a1*b.y; acc[1][2]+=a1*b.z; acc[1][3]+=a1*b.w;
        acc[2][0]+=a2*b.x; acc[2][1]+=a2*b.y; acc[2][2]+=a2*b.z; acc[2][3]+=a2*b.w;
        acc[3][0]+=a3*b.x; acc[3][1]+=a3*b.y; acc[3][2]+=a3*b.z; acc[3][3]+=a3*b.w;
    }
    #pragma unroll
    for (int i = 0; i < 4; i++) {
        int m = m0 + 4 * ty + i;
        if (m < NN) {
            float4 base = *(const float4*)&nf[(size_t)m * 64 + n0];
            *(float4*)&out[(size_t)m * 64 + n0] = make_float4(
                base.x + acc[i][0], base.y + acc[i][1], base.z + acc[i][2], base.w + acc[i][3]);
        }
    }
}

// ==================== launch ====================
extern "C" void kernel_launch(void* const* d_in, const int* in_sizes, int n_in,
                              void* d_out, int out_size) {
    const float* nf   = (const float*)d_in[0];
    const float* ef   = (const float*)d_in[1];
    const int*   src  = (const int*)d_in[2];
    const int*   dst  = (const int*)d_in[3];
    const float* rbf  = (const float*)d_in[4];
    const float* snw  = (const float*)d_in[5];
    const float* sew  = (const float*)d_in[6];
    const float* eW1  = (const float*)d_in[7];
    const float* eb1  = (const float*)d_in[8];
    const float* eW2  = (const float*)d_in[9];
    const float* eb2  = (const float*)d_in[10];
    const float* egW1 = (const float*)d_in[11];
    const float* egb1 = (const float*)d_in[12];
    const float* egW2 = (const float*)d_in[13];
    const float* egb2 = (const float*)d_in[14];
    const float* nW1  = (const float*)d_in[15];
    const float* nb1  = (const float*)d_in[16];
    const float* nW2  = (const float*)d_in[17];
    const float* nb2  = (const float*)d_in[18];
    const float* ngW1 = (const float*)d_in[19];
    const float* ngb1 = (const float*)d_in[20];
    const float* ngW2 = (const float*)d_in[21];
    const float* ngb2 = (const float*)d_in[22];
    const float* WoutM = (const float*)d_in[23];
    const float* nwf  = (const float*)d_in[24];
    const float* ewf  = (const float*)d_in[25];

    int E = in_sizes[2];
    float* outNode = (float*)d_out;
    float* outEdge = outNode + (size_t)NN * 64;

    const int ESM = 28480 * 4;   // 113920 B
    const int PSM = 17408 * 4;   // 69632 B
    static int configured = 0;
    if (!configured) {
        cudaFuncSetAttribute(edge_mma_kernel<false>, cudaFuncAttributeMaxDynamicSharedMemorySize, ESM);
        cudaFuncSetAttribute(edge_mma_kernel<true>,  cudaFuncAttributeMaxDynamicSharedMemorySize, ESM);
        cudaFuncSetAttribute(proj_mma_kernel, cudaFuncAttributeMaxDynamicSharedMemorySize, PSM);
        configured = 1;
    }

    dim3 gP((NN + 127) / 128, 4);
    proj_mma_kernel<<<gP, 256, PSM>>>(nf, eW1, egW1, nW1, ngW1);

    zero_agg_kernel<<<((size_t)NN * 64 + 255) / 256, 256>>>();

    int gE = (E + 127) / 128;
    edge_mma_kernel<false><<<gE, 256, ESM>>>(
        ef, src, dst, rbf, sew,
        eW1, eb1, eW2, eb2, egW1, egb1, egW2, egb2, ewf, outEdge, E);
    edge_mma_kernel<true><<<gE, 256, ESM>>>(
        outEdge, src, dst, rbf, snw,
        nW1, nb1, nW2, nb2, ngW1, ngb1, ngW2, ngb2, nwf, nullptr, E);

    nodeout_kernel<<<(NN + 63) / 64, 256>>>(nf, WoutM, outNode);
}

// round 8
// speedup vs baseline: 1.6182x; 1.1012x over previous
#include <cuda_runtime.h>

#define NN 50000

__device__ float g_P[(size_t)8 * NN * 64];
__device__ float g_agg[(size_t)NN * 64];

__device__ __forceinline__ float sigm_(float x) { return __fdividef(1.f, 1.f + __expf(-x)); }
__device__ __forceinline__ float silu_(float x) { return x * sigm_(x); }
__device__ __forceinline__ float tf32r(float x) {
    float y; asm("cvt.rna.tf32.f32 %0, %1;" : "=f"(y) : "f"(x)); return y;
}

// m16n8k8 tf32 HMMA, D += A*B (C==D)
__device__ __forceinline__ void mma8(float* d, const unsigned* a, const unsigned* b) {
    asm volatile("mma.sync.aligned.m16n8k8.row.col.f32.tf32.tf32.f32 "
        "{%0,%1,%2,%3},{%4,%5,%6,%7},{%8,%9},{%0,%1,%2,%3};"
        : "+f"(d[0]), "+f"(d[1]), "+f"(d[2]), "+f"(d[3])
        : "r"(a[0]), "r"(a[1]), "r"(a[2]), "r"(a[3]), "r"(b[0]), "r"(b[1]));
}

// ==================== projection kernel ====================
__global__ __launch_bounds__(256) void proj_mma_kernel(
    const float* __restrict__ nf, const float* __restrict__ eW1,
    const float* __restrict__ egW1, const float* __restrict__ nW1,
    const float* __restrict__ ngW1)
{
    extern __shared__ float sm[];
    float* sB = sm;           // 64 x 136
    float* sA = sm + 8704;    // 128 x 68

    int tid = threadIdx.x;
    int g = blockIdx.y;
    const float* W = (g == 0) ? eW1 : (g == 1) ? egW1 : (g == 2) ? nW1 : ngW1;
    int m0 = blockIdx.x * 128;

    for (int i = tid; i < 64 * 128; i += 256) {
        int k = i >> 7, n = i & 127;
        float v = (n < 64) ? W[k * 64 + n] : W[(128 + k) * 64 + (n - 64)];
        sB[k * 136 + n] = tf32r(v);
    }
    for (int i = tid; i < 128 * 64; i += 256) {
        int m = i >> 6, k = i & 63;
        int node = m0 + m;
        sA[m * 68 + k] = tf32r(node < NN ? nf[(size_t)node * 64 + k] : 0.f);
    }
    __syncthreads();

    int lane = tid & 31, w = tid >> 5, gid = lane >> 2, tig = lane & 3;
    int r0 = 16 * w + gid, r1 = r0 + 8;

    float acc[16][4];
    #pragma unroll
    for (int nt = 0; nt < 16; nt++)
        acc[nt][0] = acc[nt][1] = acc[nt][2] = acc[nt][3] = 0.f;

    #pragma unroll 2
    for (int kt = 0; kt < 8; kt++) {
        int k0 = kt * 8;
        unsigned a[4];
        a[0] = __float_as_uint(sA[r0 * 68 + k0 + tig]);
        a[1] = __float_as_uint(sA[r1 * 68 + k0 + tig]);
        a[2] = __float_as_uint(sA[r0 * 68 + k0 + tig + 4]);
        a[3] = __float_as_uint(sA[r1 * 68 + k0 + tig + 4]);
        const float* bp0 = sB + (k0 + tig) * 136 + gid;
        const float* bp1 = bp0 + 4 * 136;
        #pragma unroll
        for (int nt = 0; nt < 16; nt++) {
            unsigned b[2] = { __float_as_uint(bp0[8 * nt]), __float_as_uint(bp1[8 * nt]) };
            mma8(acc[nt], a, b);
        }
    }

    int n0g = m0 + r0, n1g = m0 + r1;
    #pragma unroll
    for (int nt = 0; nt < 16; nt++) {
        int slot = 2 * g + (nt >> 3);
        int c = ((nt & 7) << 3) + 2 * tig;
        float* base = g_P + (size_t)slot * NN * 64;
        if (n0g < NN) *(float2*)(base + (size_t)n0g * 64 + c) = make_float2(acc[nt][0], acc[nt][1]);
        if (n1g < NN) *(float2*)(base + (size_t)n1g * 64 + c) = make_float2(acc[nt][2], acc[nt][3]);
    }
}

__global__ void zero_agg_kernel() {
    size_t i = (size_t)blockIdx.x * 256 + threadIdx.x;
    if (i < (size_t)NN * 64) g_agg[i] = 0.f;
}

// ==================== fused edge+node kernel ====================
// 128 edges/CTA, 256 threads (8 warps). Warp-private rows; barriers only at
// weight reload between the edge half and the node half.
__global__ void __launch_bounds__(256, 2) fused_edge_kernel(
    const float* __restrict__ ef, const int* __restrict__ src,
    const int* __restrict__ dst, const float* __restrict__ rbf,
    const float* __restrict__ sew, const float* __restrict__ snw,
    const float* __restrict__ eW1, const float* __restrict__ eb1,
    const float* __restrict__ eW2, const float* __restrict__ eb2,
    const float* __restrict__ egW1, const float* __restrict__ egb1,
    const float* __restrict__ egW2, const float* __restrict__ egb2,
    const float* __restrict__ nW1, const float* __restrict__ nb1,
    const float* __restrict__ nW2, const float* __restrict__ nb2,
    const float* __restrict__ ngW1, const float* __restrict__ ngb1,
    const float* __restrict__ ngW2, const float* __restrict__ ngb2,
    const float* __restrict__ ewf, const float* __restrict__ nwf,
    float* __restrict__ outEdge, int E)
{
    extern __shared__ float sm[];
    float* sB1  = sm;            // 8704: phase1 weights [k][n] n<64=h, n>=64=g
    float* sB2  = sm + 8704;     // 8704: phase2 weights
    float* sSt  = sm + 17408;    // 8704: warp-private stage [128][68]
    float* sWF  = sm + 26112;    // 576
    float* sRBF = sm + 26688;    // 1280 (stride 10)
    float* sBias = sm + 27968;   // 256: b1 | gb1 | b2 | gb2
    // total 28224 floats = 112896 B

    int tid = threadIdx.x;
    int e0 = blockIdx.x * 128;

    // ---- load edge-phase weights ----
    for (int i = tid; i < 64 * 128; i += 256) {
        int k = i >> 7, n = i & 127;
        sB1[k * 136 + n] = tf32r(n < 64 ? eW1[(64 + k) * 64 + n] : egW1[(64 + k) * 64 + (n - 64)]);
        sB2[k * 136 + n] = tf32r(n < 64 ? eW2[k * 64 + n] : egW2[k * 64 + (n - 64)]);
    }
    for (int i = tid; i < 576; i += 256) sWF[i] = ewf[i];
    for (int i = tid; i < 128 * 9; i += 256) {
        int m = i / 9, r = i - 9 * m;
        int e = e0 + m;
        sRBF[m * 10 + r] = (e < E) ? rbf[(size_t)e * 9 + r] : 0.f;
    }
    if (tid < 64) {
        sBias[tid] = eb1[tid]; sBias[64 + tid] = egb1[tid];
        sBias[128 + tid] = eb2[tid]; sBias[192 + tid] = egb2[tid];
    }
    __syncthreads();

    int lane = tid & 31, w = tid >> 5, gid = lane >> 2, tig = lane & 3;
    int r0 = 16 * w + gid, r1 = r0 + 8;
    size_t eg0 = (size_t)e0 + r0, eg1 = (size_t)e0 + r1;
    bool v0 = eg0 < (size_t)E, v1 = eg1 < (size_t)E;
    int s0 = v0 ? src[eg0] : 0, d0 = v0 ? dst[eg0] : 0;
    int s1 = v1 ? src[eg1] : 0, d1 = v1 ? dst[eg1] : 0;

    // ---- prefetch ef A-fragments (tf32) ----
    unsigned efa[8][4];
    #pragma unroll
    for (int kt = 0; kt < 8; kt++) {
        int k0 = 8 * kt + tig;
        efa[kt][0] = __float_as_uint(tf32r(v0 ? ef[eg0 * 64 + k0] : 0.f));
        efa[kt][1] = __float_as_uint(tf32r(v1 ? ef[eg1 * 64 + k0] : 0.f));
        efa[kt][2] = __float_as_uint(tf32r(v0 ? ef[eg0 * 64 + k0 + 4] : 0.f));
        efa[kt][3] = __float_as_uint(tf32r(v1 ? ef[eg1 * 64 + k0 + 4] : 0.f));
    }

    float acc[16][4];
    float rb0[9], rb1[9];
    #pragma unroll
    for (int r = 0; r < 9; r++) { rb0[r] = sRBF[r0 * 10 + r]; rb1[r] = sRBF[r1 * 10 + r]; }

    // ================= EDGE HALF =================
    {
        const float* Pi  = g_P + (size_t)0 * NN * 64;
        const float* Pj  = g_P + (size_t)1 * NN * 64;
        const float* gPi = g_P + (size_t)2 * NN * 64;
        const float* gPj = g_P + (size_t)3 * NN * 64;
        #pragma unroll
        for (int nt = 0; nt < 16; nt++) {
            int c = ((nt & 7) << 3) + 2 * tig;
            const float* Ai = (nt < 8) ? Pi : gPi;
            const float* Aj = (nt < 8) ? Pj : gPj;
            const float* bb = (nt < 8) ? sBias : (sBias + 64);
            float2 i0 = *(const float2*)(Ai + (size_t)s0 * 64 + c);
            float2 j0 = *(const float2*)(Aj + (size_t)d0 * 64 + c);
            float2 i1 = *(const float2*)(Ai + (size_t)s1 * 64 + c);
            float2 j1 = *(const float2*)(Aj + (size_t)d1 * 64 + c);
            float bx = bb[c], by = bb[c + 1];
            acc[nt][0] = i0.x + j0.x + bx; acc[nt][1] = i0.y + j0.y + by;
            acc[nt][2] = i1.x + j1.x + bx; acc[nt][3] = i1.y + j1.y + by;
        }
        // phase1 MMA
        #pragma unroll 2
        for (int kt = 0; kt < 8; kt++) {
            const float* bp0 = sB1 + (8 * kt + tig) * 136 + gid;
            const float* bp1 = bp0 + 4 * 136;
            #pragma unroll
            for (int nt = 0; nt < 16; nt++) {
                unsigned b[2] = { __float_as_uint(bp0[8 * nt]), __float_as_uint(bp1[8 * nt]) };
                mma8(acc[nt], efa[kt], b);
            }
        }
        // stage h (warp-private rows), zero acc[0..7]
        #pragma unroll
        for (int nt = 0; nt < 8; nt++) {
            int c = 8 * nt + 2 * tig;
            *(float2*)(sSt + r0 * 68 + c) = make_float2(tf32r(silu_(acc[nt][0])), tf32r(silu_(acc[nt][1])));
            *(float2*)(sSt + r1 * 68 + c) = make_float2(tf32r(silu_(acc[nt][2])), tf32r(silu_(acc[nt][3])));
            acc[nt][0] = acc[nt][1] = acc[nt][2] = acc[nt][3] = 0.f;
        }
        __syncwarp();
        // phase2-h
        #pragma unroll 2
        for (int kt = 0; kt < 8; kt++) {
            int k0 = 8 * kt;
            unsigned a[4];
            a[0] = __float_as_uint(sSt[r0 * 68 + k0 + tig]);
            a[1] = __float_as_uint(sSt[r1 * 68 + k0 + tig]);
            a[2] = __float_as_uint(sSt[r0 * 68 + k0 + tig + 4]);
            a[3] = __float_as_uint(sSt[r1 * 68 + k0 + tig + 4]);
            const float* bp0 = sB2 + (k0 + tig) * 136 + gid;
            const float* bp1 = bp0 + 4 * 136;
            #pragma unroll
            for (int nt = 0; nt < 8; nt++) {
                unsigned b[2] = { __float_as_uint(bp0[8 * nt]), __float_as_uint(bp1[8 * nt]) };
                mma8(acc[nt], a, b);
            }
        }
        __syncwarp();
        // stage g, zero acc[8..15]
        #pragma unroll
        for (int nt = 8; nt < 16; nt++) {
            int c = 8 * (nt - 8) + 2 * tig;
            *(float2*)(sSt + r0 * 68 + c) = make_float2(tf32r(silu_(acc[nt][0])), tf32r(silu_(acc[nt][1])));
            *(float2*)(sSt + r1 * 68 + c) = make_float2(tf32r(silu_(acc[nt][2])), tf32r(silu_(acc[nt][3])));
            acc[nt][0] = acc[nt][1] = acc[nt][2] = acc[nt][3] = 0.f;
        }
        __syncwarp();
        // phase2-g
        #pragma unroll 2
        for (int kt = 0; kt < 8; kt++) {
            int k0 = 8 * kt;
            unsigned a[4];
            a[0] = __float_as_uint(sSt[r0 * 68 + k0 + tig]);
            a[1] = __float_as_uint(sSt[r1 * 68 + k0 + tig]);
            a[2] = __float_as_uint(sSt[r0 * 68 + k0 + tig + 4]);
            a[3] = __float_as_uint(sSt[r1 * 68 + k0 + tig + 4]);
            const float* bp0 = sB2 + (k0 + tig) * 136 + 64 + gid;
            const float* bp1 = bp0 + 4 * 136;
            #pragma unroll
            for (int nt = 8; nt < 16; nt++) {
                unsigned b[2] = { __float_as_uint(bp0[8 * (nt - 8)]), __float_as_uint(bp1[8 * (nt - 8)]) };
                mma8(acc[nt], a, b);
            }
        }
        __syncwarp();
        // edge epilogue: new_ef -> global out + tf32 into sSt (warp-private rows)
        #pragma unroll
        for (int nt = 0; nt < 8; nt++) {
            int c = 8 * nt + 2 * tig;
            float b2x = sBias[128 + c], b2y = sBias[128 + c + 1];
            float gbx = sBias[192 + c], gby = sBias[192 + c + 1];
            float wf00 = 0.f, wf01 = 0.f, wf10 = 0.f, wf11 = 0.f;
            #pragma unroll
            for (int r = 0; r < 9; r++) {
                float2 wv = *(const float2*)(sWF + r * 64 + c);
                wf00 += rb0[r] * wv.x; wf01 += rb0[r] * wv.y;
                wf10 += rb1[r] * wv.x; wf11 += rb1[r] * wv.y;
            }
            float n00 = 0.f, n01 = 0.f, n10 = 0.f, n11 = 0.f;
            if (v0) {
                float2 swv = *(const float2*)(sew + eg0 * 64 + c);
                float2 ev = *(const float2*)(ef + eg0 * 64 + c);
                n00 = ev.x + silu_(acc[nt][0] + b2x) * sigm_(acc[nt + 8][0] + gbx) * wf00 * swv.x;
                n01 = ev.y + silu_(acc[nt][1] + b2y) * sigm_(acc[nt + 8][1] + gby) * wf01 * swv.y;
                *(float2*)(outEdge + eg0 * 64 + c) = make_float2(n00, n01);
            }
            if (v1) {
                float2 swv = *(const float2*)(sew + eg1 * 64 + c);
                float2 ev = *(const float2*)(ef + eg1 * 64 + c);
                n10 = ev.x + silu_(acc[nt][2] + b2x) * sigm_(acc[nt + 8][2] + gbx) * wf10 * swv.x;
                n11 = ev.y + silu_(acc[nt][3] + b2y) * sigm_(acc[nt + 8][3] + gby) * wf11 * swv.y;
                *(float2*)(outEdge + eg1 * 64 + c) = make_float2(n10, n11);
            }
            *(float2*)(sSt + r0 * 68 + c) = make_float2(tf32r(n00), tf32r(n01));
            *(float2*)(sSt + r1 * 68 + c) = make_float2(tf32r(n10), tf32r(n11));
        }
    }

    // ---- swap to node-phase weights ----
    __syncthreads();
    for (int i = tid; i < 64 * 128; i += 256) {
        int k = i >> 7, n = i & 127;
        sB1[k * 136 + n] = tf32r(n < 64 ? nW1[(64 + k) * 64 + n] : ngW1[(64 + k) * 64 + (n - 64)]);
        sB2[k * 136 + n] = tf32r(n < 64 ? nW2[k * 64 + n] : ngW2[k * 64 + (n - 64)]);
    }
    for (int i = tid; i < 576; i += 256) sWF[i] = nwf[i];
    if (tid < 64) {
        sBias[tid] = nb1[tid]; sBias[64 + tid] = ngb1[tid];
        sBias[128 + tid] = nb2[tid]; sBias[192 + tid] = ngb2[tid];
    }
    __syncthreads();

    // ================= NODE HALF =================
    {
        const float* Pi  = g_P + (size_t)4 * NN * 64;
        const float* Pj  = g_P + (size_t)5 * NN * 64;
        const float* gPi = g_P + (size_t)6 * NN * 64;
        const float* gPj = g_P + (size_t)7 * NN * 64;
        #pragma unroll
        for (int nt = 0; nt < 16; nt++) {
            int c = ((nt & 7) << 3) + 2 * tig;
            const float* Ai = (nt < 8) ? Pi : gPi;
            const float* Aj = (nt < 8) ? Pj : gPj;
            const float* bb = (nt < 8) ? sBias : (sBias + 64);
            float2 i0 = *(const float2*)(Ai + (size_t)s0 * 64 + c);
            float2 j0 = *(const float2*)(Aj + (size_t)d0 * 64 + c);
            float2 i1 = *(const float2*)(Ai + (size_t)s1 * 64 + c);
            float2 j1 = *(const float2*)(Aj + (size_t)d1 * 64 + c);
            float bx = bb[c], by = bb[c + 1];
            acc[nt][0] = i0.x + j0.x + bx; acc[nt][1] = i0.y + j0.y + by;
            acc[nt][2] = i1.x + j1.x + bx; acc[nt][3] = i1.y + j1.y + by;
        }
        // phase1: A = new_ef (tf32) from sSt
        #pragma unroll 2
        for (int kt = 0; kt < 8; kt++) {
            int k0 = 8 * kt;
            unsigned a[4];
            a[0] = __float_as_uint(sSt[r0 * 68 + k0 + tig]);
            a[1] = __float_as_uint(sSt[r1 * 68 + k0 + tig]);
            a[2] = __float_as_uint(sSt[r0 * 68 + k0 + tig + 4]);
            a[3] = __float_as_uint(sSt[r1 * 68 + k0 + tig + 4]);
            const float* bp0 = sB1 + (k0 + tig) * 136 + gid;
            const float* bp1 = bp0 + 4 * 136;
            #pragma unroll
            for (int nt = 0; nt < 16; nt++) {
                unsigned b[2] = { __float_as_uint(bp0[8 * nt]), __float_as_uint(bp1[8 * nt]) };
                mma8(acc[nt], a, b);
            }
        }
        __syncwarp();
        // stage h
        #pragma unroll
        for (int nt = 0; nt < 8; nt++) {
            int c = 8 * nt + 2 * tig;
            *(float2*)(sSt + r0 * 68 + c) = make_float2(tf32r(silu_(acc[nt][0])), tf32r(silu_(acc[nt][1])));
            *(float2*)(sSt + r1 * 68 + c) = make_float2(tf32r(silu_(acc[nt][2])), tf32r(silu_(acc[nt][3])));
            acc[nt][0] = acc[nt][1] = acc[nt][2] = acc[nt][3] = 0.f;
        }
        __syncwarp();
        #pragma unroll 2
        for (int kt = 0; kt < 8; kt++) {
            int k0 = 8 * kt;
            unsigned a[4];
            a[0] = __float_as_uint(sSt[r0 * 68 + k0 + tig]);
            a[1] = __float_as_uint(sSt[r1 * 68 + k0 + tig]);
            a[2] = __float_as_uint(sSt[r0 * 68 + k0 + tig + 4]);
            a[3] = __float_as_uint(sSt[r1 * 68 + k0 + tig + 4]);
            const float* bp0 = sB2 + (k0 + tig) * 136 + gid;
            const float* bp1 = bp0 + 4 * 136;
            #pragma unroll
            for (int nt = 0; nt < 8; nt++) {
                unsigned b[2] = { __float_as_uint(bp0[8 * nt]), __float_as_uint(bp1[8 * nt]) };
                mma8(acc[nt], a, b);
            }
        }
        __syncwarp();
        // stage g
        #pragma unroll
        for (int nt = 8; nt < 16; nt++) {
            int c = 8 * (nt - 8) + 2 * tig;
            *(float2*)(sSt + r0 * 68 + c) = make_float2(tf32r(silu_(acc[nt][0])), tf32r(silu_(acc[nt][1])));
            *(float2*)(sSt + r1 * 68 + c) = make_float2(tf32r(silu_(acc[nt][2])), tf32r(silu_(acc[nt][3])));
            acc[nt][0] = acc[nt][1] = acc[nt][2] = acc[nt][3] = 0.f;
        }
        __syncwarp();
        #pragma unroll 2
        for (int kt = 0; kt < 8; kt++) {
            int k0 = 8 * kt;
            unsigned a[4];
            a[0] = __float_as_uint(sSt[r0 * 68 + k0 + tig]);
            a[1] = __float_as_uint(sSt[r1 * 68 + k0 + tig]);
            a[2] = __float_as_uint(sSt[r0 * 68 + k0 + tig + 4]);
            a[3] = __float_as_uint(sSt[r1 * 68 + k0 + tig + 4]);
            const float* bp0 = sB2 + (k0 + tig) * 136 + 64 + gid;
            const float* bp1 = bp0 + 4 * 136;
            #pragma unroll
            for (int nt = 8; nt < 16; nt++) {
                unsigned b[2] = { __float_as_uint(bp0[8 * (nt - 8)]), __float_as_uint(bp1[8 * (nt - 8)]) };
                mma8(acc[nt], a, b);
            }
        }
        // node epilogue: atomicAdd messages at dst
        #pragma unroll
        for (int nt = 0; nt < 8; nt++) {
            int c = 8 * nt + 2 * tig;
            float b2x = sBias[128 + c], b2y = sBias[128 + c + 1];
            float gbx = sBias[192 + c], gby = sBias[192 + c + 1];
            float wf00 = 0.f, wf01 = 0.f, wf10 = 0.f, wf11 = 0.f;
            #pragma unroll
            for (int r = 0; r < 9; r++) {
                float2 wv = *(const float2*)(sWF + r * 64 + c);
                wf00 += rb0[r] * wv.x; wf01 += rb0[r] * wv.y;
                wf10 += rb1[r] * wv.x; wf11 += rb1[r] * wv.y;
            }
            if (v0) {
                float2 swv = *(const float2*)(snw + eg0 * 64 + c);
                float m0 = silu_(acc[nt][0] + b2x) * sigm_(acc[nt + 8][0] + gbx) * wf00 * swv.x;
                float m1 = silu_(acc[nt][1] + b2y) * sigm_(acc[nt + 8][1] + gby) * wf01 * swv.y;
                atomicAdd(&g_agg[(size_t)d0 * 64 + c], m0);
                atomicAdd(&g_agg[(size_t)d0 * 64 + c + 1], m1);
            }
            if (v1) {
                float2 swv = *(const float2*)(snw + eg1 * 64 + c);
                float m0 = silu_(acc[nt][2] + b2x) * sigm_(acc[nt + 8][2] + gbx) * wf10 * swv.x;
                float m1 = silu_(acc[nt][3] + b2y) * sigm_(acc[nt + 8][3] + gby) * wf11 * swv.y;
                atomicAdd(&g_agg[(size_t)d1 * 64 + c], m0);
                atomicAdd(&g_agg[(size_t)d1 * 64 + c + 1], m1);
            }
        }
    }
}

// ==================== node output ====================
__global__ __launch_bounds__(256) void nodeout_kernel(
    const float* __restrict__ nf, const float* __restrict__ Wout,
    float* __restrict__ out)
{
    __shared__ float sAG[4096];
    __shared__ float sW[4096];
    int tid = threadIdx.x;
    int m0 = blockIdx.x * 64;
    for (int i = tid; i < 1024; i += 256) {
        ((float4*)sW)[i] = ((const float4*)Wout)[i];
        int m = i >> 4;
        float4 v = make_float4(0.f, 0.f, 0.f, 0.f);
        if (m0 + m < NN) v = *(const float4*)&g_agg[(size_t)(m0 + m) * 64 + 4 * (i & 15)];
        ((float4*)sAG)[i] = v;
    }
    __syncthreads();
    int tx = tid & 15, ty = tid >> 4, n0 = 4 * tx;
    float acc[4][4] = {};
    #pragma unroll 16
    for (int k = 0; k < 64; k++) {
        float a0 = sAG[(4*ty+0)*64+k], a1 = sAG[(4*ty+1)*64+k];
        float a2 = sAG[(4*ty+2)*64+k], a3 = sAG[(4*ty+3)*64+k];
        float4 b = *(const float4*)&sW[k * 64 + n0];
        acc[0][0]+=a0*b.x; acc[0][1]+=a0*b.y; acc[0][2]+=a0*b.z; acc[0][3]+=a0*b.w;
        acc[1][0]+=a1*b.x; acc[1][1]+=a1*b.y; acc[1][2]+=a1*b.z; acc[1][3]+=a1*b.w;
        acc[2][0]+=a2*b.x; acc[2][1]+=a2*b.y; acc[2][2]+=a2*b.z; acc[2][3]+=a2*b.w;
        acc[3][0]+=a3*b.x; acc[3][1]+=a3*b.y; acc[3][2]+=a3*b.z; acc[3][3]+=a3*b.w;
    }
    #pragma unroll
    for (int i = 0; i < 4; i++) {
        int m = m0 + 4 * ty + i;
        if (m < NN) {
            float4 base = *(const float4*)&nf[(size_t)m * 64 + n0];
            *(float4*)&out[(size_t)m * 64 + n0] = make_float4(
                base.x + acc[i][0], base.y + acc[i][1], base.z + acc[i][2], base.w + acc[i][3]);
        }
    }
}

// ==================== launch ====================
extern "C" void kernel_launch(void* const* d_in, const int* in_sizes, int n_in,
                              void* d_out, int out_size) {
    const float* nf   = (const float*)d_in[0];
    const float* ef   = (const float*)d_in[1];
    const int*   src  = (const int*)d_in[2];
    const int*   dst  = (const int*)d_in[3];
    const float* rbf  = (const float*)d_in[4];
    const float* snw  = (const float*)d_in[5];
    const float* sew  = (const float*)d_in[6];
    const float* eW1  = (const float*)d_in[7];
    const float* eb1  = (const float*)d_in[8];
    const float* eW2  = (const float*)d_in[9];
    const float* eb2  = (const float*)d_in[10];
    const float* egW1 = (const float*)d_in[11];
    const float* egb1 = (const float*)d_in[12];
    const float* egW2 = (const float*)d_in[13];
    const float* egb2 = (const float*)d_in[14];
    const float* nW1  = (const float*)d_in[15];
    const float* nb1  = (const float*)d_in[16];
    const float* nW2  = (const float*)d_in[17];
    const float* nb2  = (const float*)d_in[18];
    const float* ngW1 = (const float*)d_in[19];
    const float* ngb1 = (const float*)d_in[20];
    const float* ngW2 = (const float*)d_in[21];
    const float* ngb2 = (const float*)d_in[22];
    const float* WoutM = (const float*)d_in[23];
    const float* nwf  = (const float*)d_in[24];
    const float* ewf  = (const float*)d_in[25];

    int E = in_sizes[2];
    float* outNode = (float*)d_out;
    float* outEdge = outNode + (size_t)NN * 64;

    const int FSM = 28224 * 4;   // 112896 B
    const int PSM = 17408 * 4;   // 69632 B
    static int configured = 0;
    if (!configured) {
        cudaFuncSetAttribute(fused_edge_kernel, cudaFuncAttributeMaxDynamicSharedMemorySize, FSM);
        cudaFuncSetAttribute(proj_mma_kernel, cudaFuncAttributeMaxDynamicSharedMemorySize, PSM);
        configured = 1;
    }

    dim3 gP((NN + 127) / 128, 4);
    proj_mma_kernel<<<gP, 256, PSM>>>(nf, eW1, egW1, nW1, ngW1);

    zero_agg_kernel<<<((size_t)NN * 64 + 255) / 256, 256>>>();

    int gE = (E + 127) / 128;
    fused_edge_kernel<<<gE, 256, FSM>>>(
        ef, src, dst, rbf, sew, snw,
        eW1, eb1, eW2, eb2, egW1, egb1, egW2, egb2,
        nW1, nb1, nW2, nb2, ngW1, ngb1, ngW2, ngb2,
        ewf, nwf, outEdge, E);

    nodeout_kernel<<<(NN + 63) / 64, 256>>>(nf, WoutM, outNode);
}